// round 4
// baseline (speedup 1.0000x reference)
#include <cuda_runtime.h>
#include <cstdint>

#define N_MAX 100000

// ---------------- scratch (device globals; no allocation allowed) ----------------
__device__ __align__(128) float g_h1[(size_t)N_MAX * 128];    // projected layer-1 messages
__device__ __align__(128) float g_agg1[(size_t)N_MAX * 128];  // layer-1 aggregation
__device__ __align__(128) float g_h2[(size_t)N_MAX * 40];     // projected layer-2 messages
__device__ int   g_dout[N_MAX];
__device__ int   g_din[N_MAX];
__device__ float g_rso[N_MAX];   // rsqrt(max(deg_out,1))
__device__ float g_rsi[N_MAX];   // rsqrt(max(deg_in,1))

// ---------------- zero everything that needs zeroing, in one pass ----------------
__global__ void zero_all_kernel(float4* __restrict__ out, int N) {
    int i = blockIdx.x * blockDim.x + threadIdx.x;
    int n32 = N * 32;           // agg1 as float4
    if (i < n32) reinterpret_cast<float4*>(g_agg1)[i] = make_float4(0.f, 0.f, 0.f, 0.f);
    if (i < N * 10) out[i] = make_float4(0.f, 0.f, 0.f, 0.f);   // d_out (N*40 floats)
    if (i < N) { g_dout[i] = 0; g_din[i] = 0; }
}

// ---------------- degrees ----------------
__global__ void degree_kernel(const int* __restrict__ src, const int* __restrict__ dst, int E) {
    int e = blockIdx.x * blockDim.x + threadIdx.x;
    if (e < E) {
        atomicAdd(&g_dout[src[e]], 1);
        atomicAdd(&g_din[dst[e]], 1);
    }
}

__global__ void rsqrt_kernel(int N) {
    int i = blockIdx.x * blockDim.x + threadIdx.x;
    if (i < N) {
        g_rso[i] = rsqrtf((float)max(g_dout[i], 1));
        g_rsi[i] = rsqrtf((float)max(g_din[i], 1));
    }
}

// ---------------- GEMM1: h1 = (x * rs_out) @ W1   [N,256]x[256,128] ----------------
// 128x128 block tile (N=128 is the full width), BK=8, 256 threads, 8x8 micro-tile.
__global__ __launch_bounds__(256) void gemm1_kernel(const float* __restrict__ x,
                                                    const float* __restrict__ W1, int N) {
    __shared__ float As[8][128];   // k-major (transposed A tile)
    __shared__ float Bs[8][128];

    const int tid = threadIdx.x;
    const int block_row = blockIdx.x * 128;
    const int tr = tid >> 4;        // 0..15
    const int tc = tid & 15;        // 0..15

    // A-tile load mapping: thread -> (row, 4 consecutive k)
    const int a_row = tid >> 1;
    const int a_k4  = (tid & 1) * 4;
    const int g_row = block_row + a_row;
    const bool row_ok = (g_row < N);
    const float rs = row_ok ? g_rso[g_row] : 0.f;
    const float* a_base = x + (size_t)g_row * 256;

    // B-tile load mapping: thread -> (k, 4 consecutive n)
    const int b_k = tid >> 5;
    const int b_n = (tid & 31) * 4;

    float acc[8][8];
#pragma unroll
    for (int i = 0; i < 8; i++)
#pragma unroll
        for (int j = 0; j < 8; j++) acc[i][j] = 0.f;

    for (int k0 = 0; k0 < 256; k0 += 8) {
        float4 av = make_float4(0.f, 0.f, 0.f, 0.f);
        if (row_ok) av = *reinterpret_cast<const float4*>(a_base + k0 + a_k4);
        As[a_k4 + 0][a_row] = av.x * rs;
        As[a_k4 + 1][a_row] = av.y * rs;
        As[a_k4 + 2][a_row] = av.z * rs;
        As[a_k4 + 3][a_row] = av.w * rs;

        float4 bv = *reinterpret_cast<const float4*>(W1 + (size_t)(k0 + b_k) * 128 + b_n);
        *reinterpret_cast<float4*>(&Bs[b_k][b_n]) = bv;
        __syncthreads();

#pragma unroll
        for (int k = 0; k < 8; k++) {
            float ar[8], br[8];
#pragma unroll
            for (int i = 0; i < 8; i++) ar[i] = As[k][tr * 8 + i];
#pragma unroll
            for (int j = 0; j < 8; j++) br[j] = Bs[k][tc * 8 + j];
#pragma unroll
            for (int i = 0; i < 8; i++)
#pragma unroll
                for (int j = 0; j < 8; j++) acc[i][j] = fmaf(ar[i], br[j], acc[i][j]);
        }
        __syncthreads();
    }

#pragma unroll
    for (int i = 0; i < 8; i++) {
        int r = block_row + tr * 8 + i;
        if (r < N) {
#pragma unroll
            for (int j = 0; j < 8; j += 4) {
                float4 v = make_float4(acc[i][j], acc[i][j + 1], acc[i][j + 2], acc[i][j + 3]);
                *reinterpret_cast<float4*>(g_h1 + (size_t)r * 128 + tc * 8 + j) = v;
            }
        }
    }
}

// ---------------- scatter1: agg1[dst] += h1[src], 128 floats/edge, 1 warp/edge ----------------
__global__ __launch_bounds__(256) void scatter1_kernel(const int* __restrict__ src,
                                                       const int* __restrict__ dst, int E) {
    int e = blockIdx.x * 8 + (threadIdx.x >> 5);
    if (e >= E) return;
    int lane = threadIdx.x & 31;
    int s = src[e];
    int d = dst[e];
    float4 v = *reinterpret_cast<const float4*>(g_h1 + (size_t)s * 128 + lane * 4);
    float* p = g_agg1 + (size_t)d * 128 + lane * 4;
    asm volatile("red.global.add.v4.f32 [%0], {%1, %2, %3, %4};"
                 :: "l"(p), "f"(v.x), "f"(v.y), "f"(v.z), "f"(v.w) : "memory");
}

// ---------------- GEMM2: h2 = (relu(agg1 * rs_in + b1) * rs_out) @ W2 [N,128]x[128,40] -------
// The staged rows get BOTH the layer-1 epilogue (rsi, b1, relu) AND the layer-2
// pre-normalization (rso) — the reference applies rsqrt(deg_out) at the start of
// every GCN layer.
// Block = 32 rows, whole K=128 staged in smem, W2 fully resident in smem.
// smem: As 32*129*4 = 16512 B + Ws 128*40*4 = 20480 B = 36992 B < 48 KB static limit.
__global__ __launch_bounds__(256) void gemm2_kernel(const float* __restrict__ W2,
                                                    const float* __restrict__ b1, int N) {
    __shared__ float As[32][129];    // +1 pad: conflict-free column reads
    __shared__ float Ws[128][40];

    const int tid = threadIdx.x;
    const int row0 = blockIdx.x * 32;

    for (int i = tid; i < 128 * 40; i += 256) Ws[i / 40][i % 40] = W2[i];

    for (int l = tid * 4; l < 32 * 128; l += 256 * 4) {
        int r = l >> 7;
        int k = l & 127;
        int gr = row0 + r;
        float4 v = make_float4(0.f, 0.f, 0.f, 0.f);
        if (gr < N) {
            v = *reinterpret_cast<const float4*>(g_agg1 + (size_t)gr * 128 + k);
            float s  = g_rsi[gr];   // layer-1 epilogue normalization
            float so = g_rso[gr];   // layer-2 pre-normalization
            v.x = fmaxf(fmaf(v.x, s, b1[k + 0]), 0.f) * so;
            v.y = fmaxf(fmaf(v.y, s, b1[k + 1]), 0.f) * so;
            v.z = fmaxf(fmaf(v.z, s, b1[k + 2]), 0.f) * so;
            v.w = fmaxf(fmaf(v.w, s, b1[k + 3]), 0.f) * so;
        }
        As[r][k + 0] = v.x; As[r][k + 1] = v.y; As[r][k + 2] = v.z; As[r][k + 3] = v.w;
    }
    __syncthreads();

    const int row = tid & 31;       // one warp spans 32 rows
    const int cg = tid >> 5;        // 0..7 -> 5 columns each
    float acc[5];
#pragma unroll
    for (int j = 0; j < 5; j++) acc[j] = 0.f;

#pragma unroll 8
    for (int k = 0; k < 128; k++) {
        float a = As[row][k];
#pragma unroll
        for (int j = 0; j < 5; j++) acc[j] = fmaf(a, Ws[k][cg * 5 + j], acc[j]);
    }

    int gr = row0 + row;
    if (gr < N) {
#pragma unroll
        for (int j = 0; j < 5; j++) g_h2[(size_t)gr * 40 + cg * 5 + j] = acc[j];
    }
}

// ---------------- scatter2: out[dst] += h2[src], 40 floats/edge = 10 float4 tasks ----------------
__global__ __launch_bounds__(256) void scatter2_kernel(const int* __restrict__ src,
                                                       const int* __restrict__ dst,
                                                       float* __restrict__ out, int E) {
    int t = blockIdx.x * blockDim.x + threadIdx.x;
    int e = t / 10;
    int c = t - e * 10;
    if (e >= E) return;
    int s = src[e];
    int d = dst[e];
    float4 v = *reinterpret_cast<const float4*>(g_h2 + (size_t)s * 40 + c * 4);
    float* p = out + (size_t)d * 40 + c * 4;
    asm volatile("red.global.add.v4.f32 [%0], {%1, %2, %3, %4};"
                 :: "l"(p), "f"(v.x), "f"(v.y), "f"(v.z), "f"(v.w) : "memory");
}

// ---------------- finalize: out = out * rs_in + b2 (in place) ----------------
__global__ void finalize_kernel(float* __restrict__ out, const float* __restrict__ b2, int N) {
    int t = blockIdx.x * blockDim.x + threadIdx.x;
    if (t < N * 40) {
        int r = t / 40;
        int c = t - r * 40;
        out[t] = fmaf(out[t], g_rsi[r], b2[c]);
    }
}

// ---------------- launch ----------------
extern "C" void kernel_launch(void* const* d_in, const int* in_sizes, int n_in,
                              void* d_out, int out_size) {
    const float* x  = (const float*)d_in[0];
    const float* W1 = (const float*)d_in[1];
    const float* b1 = (const float*)d_in[2];
    const float* W2 = (const float*)d_in[3];
    const float* b2 = (const float*)d_in[4];
    const int*  src = (const int*)d_in[5];
    const int*  dst = (const int*)d_in[6];

    const int N = in_sizes[0] / 256;
    const int E = in_sizes[5];

    float* out = (float*)d_out;

    // 1. zero agg1, d_out, degree counters
    {
        int tot = N * 32;  // largest span (agg1 float4 count)
        zero_all_kernel<<<(tot + 255) / 256, 256>>>((float4*)out, N);
    }
    // 2. degrees + normalizers
    degree_kernel<<<(E + 255) / 256, 256>>>(src, dst, E);
    rsqrt_kernel<<<(N + 255) / 256, 256>>>(N);
    // 3. layer-1 projection
    gemm1_kernel<<<(N + 127) / 128, 256>>>(x, W1, N);
    // 4. layer-1 aggregation (1 warp/edge)
    scatter1_kernel<<<(E + 7) / 8, 256>>>(src, dst, E);
    // 5. layer-2 projection (fused l1-epilogue + relu + l2-prenorm)
    gemm2_kernel<<<(N + 31) / 32, 256>>>(W2, b1, N);
    // 6. layer-2 aggregation into d_out
    {
        long long tasks = (long long)E * 10;
        scatter2_kernel<<<(int)((tasks + 255) / 256), 256>>>(src, dst, out, E);
    }
    // 7. epilogue
    finalize_kernel<<<(N * 40 + 255) / 256, 256>>>(out, b2, N);
}

// round 5
// speedup vs baseline: 1.6697x; 1.6697x over previous
#include <cuda_runtime.h>
#include <cstdint>

#define N_MAX 100000
#define E_MAX 3200000
#define SCAN_BLK 1024
#define SCAN_NBLK ((N_MAX + SCAN_BLK - 1) / SCAN_BLK)   // 98

// ---------------- scratch (device globals; no allocation allowed) ----------------
__device__ __align__(128) float g_h1[(size_t)N_MAX * 128];    // projected layer-1 messages
__device__ __align__(128) float g_agg1[(size_t)N_MAX * 128];  // layer-1 result (activated+prenormed)
__device__ __align__(128) float g_h2[(size_t)N_MAX * 40];     // projected layer-2 messages
__device__ int   g_din[N_MAX];           // raw in-degree (dst counts)
__device__ int   g_dout[N_MAX];          // raw out-degree (src counts)
__device__ float g_rso[N_MAX];           // rsqrt(max(deg_out,1))
__device__ float g_rsi[N_MAX];           // rsqrt(max(deg_in,1))
__device__ int   g_off[N_MAX + 1024];    // CSR row offsets (exclusive scan of g_din)
__device__ int   g_cursor[N_MAX];        // binning cursors
__device__ int   g_bsum[SCAN_NBLK + 32]; // scan block sums
__device__ int   g_csr_src[E_MAX];       // src node ids grouped by dst

// ---------------- zero degree counters ----------------
__global__ void zero_counts_kernel(int N) {
    int i = blockIdx.x * blockDim.x + threadIdx.x;
    if (i < N) { g_din[i] = 0; g_dout[i] = 0; }
}

// ---------------- degrees / histogram ----------------
__global__ void degree_kernel(const int* __restrict__ src, const int* __restrict__ dst, int E) {
    int e = blockIdx.x * blockDim.x + threadIdx.x;
    if (e < E) {
        atomicAdd(&g_dout[src[e]], 1);
        atomicAdd(&g_din[dst[e]], 1);
    }
}

__global__ void rsqrt_kernel(int N) {
    int i = blockIdx.x * blockDim.x + threadIdx.x;
    if (i < N) {
        g_rso[i] = rsqrtf((float)max(g_dout[i], 1));
        g_rsi[i] = rsqrtf((float)max(g_din[i], 1));
    }
}

// ---------------- scan (exclusive) of g_din into g_off, 3 phases ----------------
__global__ __launch_bounds__(SCAN_BLK) void scan_phase1_kernel(int N) {
    __shared__ int sh[SCAN_BLK];
    int i = blockIdx.x * SCAN_BLK + threadIdx.x;
    int v = (i < N) ? g_din[i] : 0;
    sh[threadIdx.x] = v;
    __syncthreads();
#pragma unroll
    for (int d = 1; d < SCAN_BLK; d <<= 1) {
        int t = (threadIdx.x >= d) ? sh[threadIdx.x - d] : 0;
        __syncthreads();
        sh[threadIdx.x] += t;
        __syncthreads();
    }
    if (i < N) g_off[i] = sh[threadIdx.x] - v;           // exclusive within block
    if (threadIdx.x == SCAN_BLK - 1) g_bsum[blockIdx.x] = sh[SCAN_BLK - 1];
}

__global__ __launch_bounds__(128) void scan_phase2_kernel(int nb) {
    __shared__ int sh[128];
    int t = threadIdx.x;
    int v = (t < nb) ? g_bsum[t] : 0;
    sh[t] = v;
    __syncthreads();
#pragma unroll
    for (int d = 1; d < 128; d <<= 1) {
        int x = (t >= d) ? sh[t - d] : 0;
        __syncthreads();
        sh[t] += x;
        __syncthreads();
    }
    if (t < nb) g_bsum[t] = sh[t] - v;                   // exclusive
}

__global__ void scan_phase3_kernel(int N) {
    int i = blockIdx.x * blockDim.x + threadIdx.x;
    if (i < N) {
        int o = g_off[i] + g_bsum[i >> 10];
        g_off[i] = o;
        g_cursor[i] = o;
    }
}

// ---------------- bin: group edge srcs by dst ----------------
__global__ void bin_kernel(const int* __restrict__ src, const int* __restrict__ dst, int E) {
    int e = blockIdx.x * blockDim.x + threadIdx.x;
    if (e < E) {
        int d = dst[e];
        int pos = atomicAdd(&g_cursor[d], 1);
        g_csr_src[pos] = src[e];
    }
}

// ---------------- GEMM1: h1 = (x * rs_out) @ W1   [N,256]x[256,128] ----------------
__global__ __launch_bounds__(256) void gemm1_kernel(const float* __restrict__ x,
                                                    const float* __restrict__ W1, int N) {
    __shared__ float As[8][128];   // k-major (transposed A tile)
    __shared__ float Bs[8][128];

    const int tid = threadIdx.x;
    const int block_row = blockIdx.x * 128;
    const int tr = tid >> 4;
    const int tc = tid & 15;

    const int a_row = tid >> 1;
    const int a_k4  = (tid & 1) * 4;
    const int g_row = block_row + a_row;
    const bool row_ok = (g_row < N);
    const float rs = row_ok ? g_rso[g_row] : 0.f;
    const float* a_base = x + (size_t)g_row * 256;

    const int b_k = tid >> 5;
    const int b_n = (tid & 31) * 4;

    float acc[8][8];
#pragma unroll
    for (int i = 0; i < 8; i++)
#pragma unroll
        for (int j = 0; j < 8; j++) acc[i][j] = 0.f;

    for (int k0 = 0; k0 < 256; k0 += 8) {
        float4 av = make_float4(0.f, 0.f, 0.f, 0.f);
        if (row_ok) av = *reinterpret_cast<const float4*>(a_base + k0 + a_k4);
        As[a_k4 + 0][a_row] = av.x * rs;
        As[a_k4 + 1][a_row] = av.y * rs;
        As[a_k4 + 2][a_row] = av.z * rs;
        As[a_k4 + 3][a_row] = av.w * rs;

        float4 bv = *reinterpret_cast<const float4*>(W1 + (size_t)(k0 + b_k) * 128 + b_n);
        *reinterpret_cast<float4*>(&Bs[b_k][b_n]) = bv;
        __syncthreads();

#pragma unroll
        for (int k = 0; k < 8; k++) {
            float ar[8], br[8];
#pragma unroll
            for (int i = 0; i < 8; i++) ar[i] = As[k][tr * 8 + i];
#pragma unroll
            for (int j = 0; j < 8; j++) br[j] = Bs[k][tc * 8 + j];
#pragma unroll
            for (int i = 0; i < 8; i++)
#pragma unroll
                for (int j = 0; j < 8; j++) acc[i][j] = fmaf(ar[i], br[j], acc[i][j]);
        }
        __syncthreads();
    }

#pragma unroll
    for (int i = 0; i < 8; i++) {
        int r = block_row + tr * 8 + i;
        if (r < N) {
#pragma unroll
            for (int j = 0; j < 8; j += 4) {
                float4 v = make_float4(acc[i][j], acc[i][j + 1], acc[i][j + 2], acc[i][j + 3]);
                *reinterpret_cast<float4*>(g_h1 + (size_t)r * 128 + tc * 8 + j) = v;
            }
        }
    }
}

// ---------------- gather1: one warp per dst node ----------------
// agg1[node] = relu( (sum_{e: dst=node} h1[src_e]) * rsi + b1 ) * rso
// (layer-1 epilogue AND layer-2 pre-normalization fused into the single write)
__global__ __launch_bounds__(256) void gather1_kernel(const float* __restrict__ b1, int N) {
    const int wid = threadIdx.x >> 5;
    const int lane = threadIdx.x & 31;
    const int node = blockIdx.x * 8 + wid;
    if (node >= N) return;

    const int start = g_off[node];
    const int cnt = g_din[node];
    const int* __restrict__ idx = g_csr_src + start;

    float4 acc = make_float4(0.f, 0.f, 0.f, 0.f);
    int i = 0;
    for (; i + 4 <= cnt; i += 4) {
        int s0 = idx[i], s1 = idx[i + 1], s2 = idx[i + 2], s3 = idx[i + 3];
        float4 v0 = *reinterpret_cast<const float4*>(g_h1 + (size_t)s0 * 128 + lane * 4);
        float4 v1 = *reinterpret_cast<const float4*>(g_h1 + (size_t)s1 * 128 + lane * 4);
        float4 v2 = *reinterpret_cast<const float4*>(g_h1 + (size_t)s2 * 128 + lane * 4);
        float4 v3 = *reinterpret_cast<const float4*>(g_h1 + (size_t)s3 * 128 + lane * 4);
        acc.x += (v0.x + v1.x) + (v2.x + v3.x);
        acc.y += (v0.y + v1.y) + (v2.y + v3.y);
        acc.z += (v0.z + v1.z) + (v2.z + v3.z);
        acc.w += (v0.w + v1.w) + (v2.w + v3.w);
    }
    for (; i < cnt; i++) {
        int s = idx[i];
        float4 v = *reinterpret_cast<const float4*>(g_h1 + (size_t)s * 128 + lane * 4);
        acc.x += v.x; acc.y += v.y; acc.z += v.z; acc.w += v.w;
    }

    const float rsi = g_rsi[node];
    const float rso = g_rso[node];
    float4 bb = *reinterpret_cast<const float4*>(b1 + lane * 4);
    float4 r;
    r.x = fmaxf(fmaf(acc.x, rsi, bb.x), 0.f) * rso;
    r.y = fmaxf(fmaf(acc.y, rsi, bb.y), 0.f) * rso;
    r.z = fmaxf(fmaf(acc.z, rsi, bb.z), 0.f) * rso;
    r.w = fmaxf(fmaf(acc.w, rsi, bb.w), 0.f) * rso;
    *reinterpret_cast<float4*>(g_agg1 + (size_t)node * 128 + lane * 4) = r;
}

// ---------------- GEMM2: h2 = agg1 @ W2   [N,128]x[128,40] (agg1 pre-activated) ----------------
__global__ __launch_bounds__(256) void gemm2_kernel(const float* __restrict__ W2, int N) {
    __shared__ float As[32][129];
    __shared__ float Ws[128][40];

    const int tid = threadIdx.x;
    const int row0 = blockIdx.x * 32;

    for (int i = tid; i < 128 * 40; i += 256) Ws[i / 40][i % 40] = W2[i];

    for (int l = tid * 4; l < 32 * 128; l += 256 * 4) {
        int r = l >> 7;
        int k = l & 127;
        int gr = row0 + r;
        float4 v = make_float4(0.f, 0.f, 0.f, 0.f);
        if (gr < N) v = *reinterpret_cast<const float4*>(g_agg1 + (size_t)gr * 128 + k);
        As[r][k + 0] = v.x; As[r][k + 1] = v.y; As[r][k + 2] = v.z; As[r][k + 3] = v.w;
    }
    __syncthreads();

    const int row = tid & 31;
    const int cg = tid >> 5;        // 0..7 -> 5 columns each
    float acc[5];
#pragma unroll
    for (int j = 0; j < 5; j++) acc[j] = 0.f;

#pragma unroll 8
    for (int k = 0; k < 128; k++) {
        float a = As[row][k];
#pragma unroll
        for (int j = 0; j < 5; j++) acc[j] = fmaf(a, Ws[k][cg * 5 + j], acc[j]);
    }

    int gr = row0 + row;
    if (gr < N) {
#pragma unroll
        for (int j = 0; j < 5; j++) g_h2[(size_t)gr * 40 + cg * 5 + j] = acc[j];
    }
}

// ---------------- gather2: 10 threads per dst node (one float4 column each) ----------------
// out[node] = (sum_{e: dst=node} h2[src_e]) * rsi + b2    (finalize fused)
__global__ __launch_bounds__(256) void gather2_kernel(const float* __restrict__ b2,
                                                      float* __restrict__ out, int N) {
    int t = blockIdx.x * blockDim.x + threadIdx.x;
    int node = t / 10;
    int c = t - node * 10;
    if (node >= N) return;

    const int start = g_off[node];
    const int cnt = g_din[node];
    const int* __restrict__ idx = g_csr_src + start;

    float4 acc = make_float4(0.f, 0.f, 0.f, 0.f);
    int i = 0;
    for (; i + 4 <= cnt; i += 4) {
        int s0 = idx[i], s1 = idx[i + 1], s2 = idx[i + 2], s3 = idx[i + 3];
        float4 v0 = *reinterpret_cast<const float4*>(g_h2 + (size_t)s0 * 40 + c * 4);
        float4 v1 = *reinterpret_cast<const float4*>(g_h2 + (size_t)s1 * 40 + c * 4);
        float4 v2 = *reinterpret_cast<const float4*>(g_h2 + (size_t)s2 * 40 + c * 4);
        float4 v3 = *reinterpret_cast<const float4*>(g_h2 + (size_t)s3 * 40 + c * 4);
        acc.x += (v0.x + v1.x) + (v2.x + v3.x);
        acc.y += (v0.y + v1.y) + (v2.y + v3.y);
        acc.z += (v0.z + v1.z) + (v2.z + v3.z);
        acc.w += (v0.w + v1.w) + (v2.w + v3.w);
    }
    for (; i < cnt; i++) {
        int s = idx[i];
        float4 v = *reinterpret_cast<const float4*>(g_h2 + (size_t)s * 40 + c * 4);
        acc.x += v.x; acc.y += v.y; acc.z += v.z; acc.w += v.w;
    }

    const float rsi = g_rsi[node];
    float4 bb = *reinterpret_cast<const float4*>(b2 + c * 4);
    float4 r;
    r.x = fmaf(acc.x, rsi, bb.x);
    r.y = fmaf(acc.y, rsi, bb.y);
    r.z = fmaf(acc.z, rsi, bb.z);
    r.w = fmaf(acc.w, rsi, bb.w);
    *reinterpret_cast<float4*>(out + (size_t)node * 40 + c * 4) = r;
}

// ---------------- launch ----------------
extern "C" void kernel_launch(void* const* d_in, const int* in_sizes, int n_in,
                              void* d_out, int out_size) {
    const float* x  = (const float*)d_in[0];
    const float* W1 = (const float*)d_in[1];
    const float* b1 = (const float*)d_in[2];
    const float* W2 = (const float*)d_in[3];
    const float* b2 = (const float*)d_in[4];
    const int*  src = (const int*)d_in[5];
    const int*  dst = (const int*)d_in[6];

    const int N = in_sizes[0] / 256;
    const int E = in_sizes[5];

    float* out = (float*)d_out;

    // 1. zero degree counters
    zero_counts_kernel<<<(N + 255) / 256, 256>>>(N);
    // 2. degrees (doubles as CSR histogram)
    degree_kernel<<<(E + 255) / 256, 256>>>(src, dst, E);
    rsqrt_kernel<<<(N + 255) / 256, 256>>>(N);
    // 3. exclusive scan of in-degrees -> CSR offsets + cursors
    {
        int nb = (N + SCAN_BLK - 1) / SCAN_BLK;
        scan_phase1_kernel<<<nb, SCAN_BLK>>>(N);
        scan_phase2_kernel<<<1, 128>>>(nb);
        scan_phase3_kernel<<<(N + 255) / 256, 256>>>(N);
    }
    // 4. bin edges by dst
    bin_kernel<<<(E + 255) / 256, 256>>>(src, dst, E);
    // 5. layer-1 projection
    gemm1_kernel<<<(N + 127) / 128, 256>>>(x, W1, N);
    // 6. layer-1 aggregation (warp/node, epilogue + prenorm fused)
    gather1_kernel<<<(N + 7) / 8, 256>>>(b1, N);
    // 7. layer-2 projection
    gemm2_kernel<<<(N + 31) / 32, 256>>>(W2, N);
    // 8. layer-2 aggregation + finalize fused
    {
        long long tasks = (long long)N * 10;
        gather2_kernel<<<(int)((tasks + 255) / 256), 256>>>(b2, out, N);
    }
}

// round 6
// speedup vs baseline: 1.7586x; 1.0532x over previous
#include <cuda_runtime.h>
#include <cstdint>

#define N_MAX 100000
#define E_MAX 3200000
#define SCAN_BLK 1024
#define SCAN_NBLK ((N_MAX + SCAN_BLK - 1) / SCAN_BLK)   // 98

// ---------------- scratch (device globals; no allocation allowed) ----------------
__device__ __align__(128) float g_h1[(size_t)N_MAX * 128];    // projected layer-1 messages (UNSCALED)
__device__ __align__(128) float g_agg1[(size_t)N_MAX * 128];  // layer-1 result (activated+prenormed)
__device__ __align__(128) float g_h2[(size_t)N_MAX * 40];     // projected layer-2 messages
__device__ int   g_din[N_MAX];           // raw in-degree (dst counts)
__device__ int   g_dout[N_MAX];          // raw out-degree (src counts)
__device__ float g_rso[N_MAX];           // rsqrt(max(deg_out,1))
__device__ float g_rsi[N_MAX];           // rsqrt(max(deg_in,1))
__device__ int   g_off[N_MAX + 1024];    // CSR row offsets (exclusive scan of g_din)
__device__ int   g_cursor[N_MAX];        // binning cursors
__device__ int   g_bsum[SCAN_NBLK + 32]; // scan block sums
__device__ int   g_csr_src[E_MAX];       // src node ids grouped by dst

// ---------------- zero degree counters ----------------
__global__ void zero_counts_kernel(int N) {
    int i = blockIdx.x * blockDim.x + threadIdx.x;
    if (i < N) { g_din[i] = 0; g_dout[i] = 0; }
}

// ---------------- degrees / histogram ----------------
__global__ void degree_kernel(const int* __restrict__ src, const int* __restrict__ dst, int E) {
    int e = blockIdx.x * blockDim.x + threadIdx.x;
    if (e < E) {
        atomicAdd(&g_dout[src[e]], 1);
        atomicAdd(&g_din[dst[e]], 1);
    }
}

__global__ void rsqrt_kernel(int N) {
    int i = blockIdx.x * blockDim.x + threadIdx.x;
    if (i < N) {
        g_rso[i] = rsqrtf((float)max(g_dout[i], 1));
        g_rsi[i] = rsqrtf((float)max(g_din[i], 1));
    }
}

// ---------------- scan (exclusive) of g_din into g_off, 3 phases ----------------
__global__ __launch_bounds__(SCAN_BLK) void scan_phase1_kernel(int N) {
    __shared__ int sh[SCAN_BLK];
    int i = blockIdx.x * SCAN_BLK + threadIdx.x;
    int v = (i < N) ? g_din[i] : 0;
    sh[threadIdx.x] = v;
    __syncthreads();
#pragma unroll
    for (int d = 1; d < SCAN_BLK; d <<= 1) {
        int t = (threadIdx.x >= d) ? sh[threadIdx.x - d] : 0;
        __syncthreads();
        sh[threadIdx.x] += t;
        __syncthreads();
    }
    if (i < N) g_off[i] = sh[threadIdx.x] - v;           // exclusive within block
    if (threadIdx.x == SCAN_BLK - 1) g_bsum[blockIdx.x] = sh[SCAN_BLK - 1];
}

__global__ __launch_bounds__(128) void scan_phase2_kernel(int nb) {
    __shared__ int sh[128];
    int t = threadIdx.x;
    int v = (t < nb) ? g_bsum[t] : 0;
    sh[t] = v;
    __syncthreads();
#pragma unroll
    for (int d = 1; d < 128; d <<= 1) {
        int x = (t >= d) ? sh[t - d] : 0;
        __syncthreads();
        sh[t] += x;
        __syncthreads();
    }
    if (t < nb) g_bsum[t] = sh[t] - v;                   // exclusive
}

__global__ void scan_phase3_kernel(int N) {
    int i = blockIdx.x * blockDim.x + threadIdx.x;
    if (i < N) {
        int o = g_off[i] + g_bsum[i >> 10];
        g_off[i] = o;
        g_cursor[i] = o;
    }
}

// ---------------- bin: group edge srcs by dst ----------------
__global__ void bin_kernel(const int* __restrict__ src, const int* __restrict__ dst, int E) {
    int e = blockIdx.x * blockDim.x + threadIdx.x;
    if (e < E) {
        int d = dst[e];
        int pos = atomicAdd(&g_cursor[d], 1);
        g_csr_src[pos] = src[e];
    }
}

// ---------------- GEMM1: h1 = x @ W1   [N,256]x[256,128] (NO rso scaling here) ----------------
// 128x128 block tile, BK=8, 256 threads, 8x8 micro-tile, 2-stage register prefetch.
// Depends only on x and W1 -> runs concurrently with the CSR build (stream fork).
__global__ __launch_bounds__(256, 2) void gemm1_kernel(const float* __restrict__ x,
                                                       const float* __restrict__ W1, int N) {
    __shared__ float As[8][128];   // k-major (transposed A tile)
    __shared__ float Bs[8][128];

    const int tid = threadIdx.x;
    const int block_row = blockIdx.x * 128;
    const int tr = tid >> 4;
    const int tc = tid & 15;

    const int a_row = tid >> 1;
    const int a_k4  = (tid & 1) * 4;
    const int g_row = block_row + a_row;
    const bool row_ok = (g_row < N);
    const float* a_base = x + (size_t)g_row * 256;

    const int b_k = tid >> 5;
    const int b_n = (tid & 31) * 4;

    float acc[8][8];
#pragma unroll
    for (int i = 0; i < 8; i++)
#pragma unroll
        for (int j = 0; j < 8; j++) acc[i][j] = 0.f;

    // prologue: prefetch k0 = 0
    float4 av = make_float4(0.f, 0.f, 0.f, 0.f);
    if (row_ok) av = *reinterpret_cast<const float4*>(a_base + a_k4);
    float4 bv = *reinterpret_cast<const float4*>(W1 + (size_t)b_k * 128 + b_n);

    for (int k0 = 0; k0 < 256; k0 += 8) {
        As[a_k4 + 0][a_row] = av.x;
        As[a_k4 + 1][a_row] = av.y;
        As[a_k4 + 2][a_row] = av.z;
        As[a_k4 + 3][a_row] = av.w;
        *reinterpret_cast<float4*>(&Bs[b_k][b_n]) = bv;
        __syncthreads();

        // prefetch next tile while computing this one
        if (k0 + 8 < 256) {
            if (row_ok) av = *reinterpret_cast<const float4*>(a_base + k0 + 8 + a_k4);
            bv = *reinterpret_cast<const float4*>(W1 + (size_t)(k0 + 8 + b_k) * 128 + b_n);
        }

#pragma unroll
        for (int k = 0; k < 8; k++) {
            float ar[8], br[8];
#pragma unroll
            for (int i = 0; i < 8; i++) ar[i] = As[k][tr * 8 + i];
#pragma unroll
            for (int j = 0; j < 8; j++) br[j] = Bs[k][tc * 8 + j];
#pragma unroll
            for (int i = 0; i < 8; i++)
#pragma unroll
                for (int j = 0; j < 8; j++) acc[i][j] = fmaf(ar[i], br[j], acc[i][j]);
        }
        __syncthreads();
    }

#pragma unroll
    for (int i = 0; i < 8; i++) {
        int r = block_row + tr * 8 + i;
        if (r < N) {
#pragma unroll
            for (int j = 0; j < 8; j += 4) {
                float4 v = make_float4(acc[i][j], acc[i][j + 1], acc[i][j + 2], acc[i][j + 3]);
                *reinterpret_cast<float4*>(g_h1 + (size_t)r * 128 + tc * 8 + j) = v;
            }
        }
    }
}

// ---------------- gather1: one warp per dst node ----------------
// agg1[node] = relu( (sum_{e: dst=node} rso[src_e] * h1[src_e]) * rsi + b1 ) * rso[node]
// (per-src prenorm applied HERE so gemm1 has no degree dependency)
__global__ __launch_bounds__(256) void gather1_kernel(const float* __restrict__ b1, int N) {
    const int wid = threadIdx.x >> 5;
    const int lane = threadIdx.x & 31;
    const int node = blockIdx.x * 8 + wid;
    if (node >= N) return;

    const int start = g_off[node];
    const int cnt = g_din[node];
    const int* __restrict__ idx = g_csr_src + start;

    float4 acc = make_float4(0.f, 0.f, 0.f, 0.f);
    int i = 0;
    for (; i + 4 <= cnt; i += 4) {
        int s0 = idx[i], s1 = idx[i + 1], s2 = idx[i + 2], s3 = idx[i + 3];
        float w0 = g_rso[s0], w1 = g_rso[s1], w2 = g_rso[s2], w3 = g_rso[s3];
        float4 v0 = *reinterpret_cast<const float4*>(g_h1 + (size_t)s0 * 128 + lane * 4);
        float4 v1 = *reinterpret_cast<const float4*>(g_h1 + (size_t)s1 * 128 + lane * 4);
        float4 v2 = *reinterpret_cast<const float4*>(g_h1 + (size_t)s2 * 128 + lane * 4);
        float4 v3 = *reinterpret_cast<const float4*>(g_h1 + (size_t)s3 * 128 + lane * 4);
        acc.x = fmaf(v0.x, w0, fmaf(v1.x, w1, fmaf(v2.x, w2, fmaf(v3.x, w3, acc.x))));
        acc.y = fmaf(v0.y, w0, fmaf(v1.y, w1, fmaf(v2.y, w2, fmaf(v3.y, w3, acc.y))));
        acc.z = fmaf(v0.z, w0, fmaf(v1.z, w1, fmaf(v2.z, w2, fmaf(v3.z, w3, acc.z))));
        acc.w = fmaf(v0.w, w0, fmaf(v1.w, w1, fmaf(v2.w, w2, fmaf(v3.w, w3, acc.w))));
    }
    for (; i < cnt; i++) {
        int s = idx[i];
        float w = g_rso[s];
        float4 v = *reinterpret_cast<const float4*>(g_h1 + (size_t)s * 128 + lane * 4);
        acc.x = fmaf(v.x, w, acc.x);
        acc.y = fmaf(v.y, w, acc.y);
        acc.z = fmaf(v.z, w, acc.z);
        acc.w = fmaf(v.w, w, acc.w);
    }

    const float rsi = g_rsi[node];
    const float rso = g_rso[node];
    float4 bb = *reinterpret_cast<const float4*>(b1 + lane * 4);
    float4 r;
    r.x = fmaxf(fmaf(acc.x, rsi, bb.x), 0.f) * rso;
    r.y = fmaxf(fmaf(acc.y, rsi, bb.y), 0.f) * rso;
    r.z = fmaxf(fmaf(acc.z, rsi, bb.z), 0.f) * rso;
    r.w = fmaxf(fmaf(acc.w, rsi, bb.w), 0.f) * rso;
    *reinterpret_cast<float4*>(g_agg1 + (size_t)node * 128 + lane * 4) = r;
}

// ---------------- GEMM2: h2 = agg1 @ W2   [N,128]x[128,40] (agg1 pre-activated) ----------------
__global__ __launch_bounds__(256) void gemm2_kernel(const float* __restrict__ W2, int N) {
    __shared__ float As[32][129];
    __shared__ float Ws[128][40];

    const int tid = threadIdx.x;
    const int row0 = blockIdx.x * 32;

    for (int i = tid; i < 128 * 40; i += 256) Ws[i / 40][i % 40] = W2[i];

    for (int l = tid * 4; l < 32 * 128; l += 256 * 4) {
        int r = l >> 7;
        int k = l & 127;
        int gr = row0 + r;
        float4 v = make_float4(0.f, 0.f, 0.f, 0.f);
        if (gr < N) v = *reinterpret_cast<const float4*>(g_agg1 + (size_t)gr * 128 + k);
        As[r][k + 0] = v.x; As[r][k + 1] = v.y; As[r][k + 2] = v.z; As[r][k + 3] = v.w;
    }
    __syncthreads();

    const int row = tid & 31;
    const int cg = tid >> 5;        // 0..7 -> 5 columns each
    float acc[5];
#pragma unroll
    for (int j = 0; j < 5; j++) acc[j] = 0.f;

#pragma unroll 8
    for (int k = 0; k < 128; k++) {
        float a = As[row][k];
#pragma unroll
        for (int j = 0; j < 5; j++) acc[j] = fmaf(a, Ws[k][cg * 5 + j], acc[j]);
    }

    int gr = row0 + row;
    if (gr < N) {
#pragma unroll
        for (int j = 0; j < 5; j++) g_h2[(size_t)gr * 40 + cg * 5 + j] = acc[j];
    }
}

// ---------------- gather2: 10 threads per dst node (one float4 column each) ----------------
// out[node] = (sum_{e: dst=node} h2[src_e]) * rsi + b2    (finalize fused)
__global__ __launch_bounds__(256) void gather2_kernel(const float* __restrict__ b2,
                                                      float* __restrict__ out, int N) {
    int t = blockIdx.x * blockDim.x + threadIdx.x;
    int node = t / 10;
    int c = t - node * 10;
    if (node >= N) return;

    const int start = g_off[node];
    const int cnt = g_din[node];
    const int* __restrict__ idx = g_csr_src + start;

    float4 acc = make_float4(0.f, 0.f, 0.f, 0.f);
    int i = 0;
    for (; i + 4 <= cnt; i += 4) {
        int s0 = idx[i], s1 = idx[i + 1], s2 = idx[i + 2], s3 = idx[i + 3];
        float4 v0 = *reinterpret_cast<const float4*>(g_h2 + (size_t)s0 * 40 + c * 4);
        float4 v1 = *reinterpret_cast<const float4*>(g_h2 + (size_t)s1 * 40 + c * 4);
        float4 v2 = *reinterpret_cast<const float4*>(g_h2 + (size_t)s2 * 40 + c * 4);
        float4 v3 = *reinterpret_cast<const float4*>(g_h2 + (size_t)s3 * 40 + c * 4);
        acc.x += (v0.x + v1.x) + (v2.x + v3.x);
        acc.y += (v0.y + v1.y) + (v2.y + v3.y);
        acc.z += (v0.z + v1.z) + (v2.z + v3.z);
        acc.w += (v0.w + v1.w) + (v2.w + v3.w);
    }
    for (; i < cnt; i++) {
        int s = idx[i];
        float4 v = *reinterpret_cast<const float4*>(g_h2 + (size_t)s * 40 + c * 4);
        acc.x += v.x; acc.y += v.y; acc.z += v.z; acc.w += v.w;
    }

    const float rsi = g_rsi[node];
    float4 bb = *reinterpret_cast<const float4*>(b2 + c * 4);
    float4 r;
    r.x = fmaf(acc.x, rsi, bb.x);
    r.y = fmaf(acc.y, rsi, bb.y);
    r.z = fmaf(acc.z, rsi, bb.z);
    r.w = fmaf(acc.w, rsi, bb.w);
    *reinterpret_cast<float4*>(out + (size_t)node * 40 + c * 4) = r;
}

// ---------------- launch (stream fork: gemm1 || CSR build) ----------------
extern "C" void kernel_launch(void* const* d_in, const int* in_sizes, int n_in,
                              void* d_out, int out_size) {
    const float* x  = (const float*)d_in[0];
    const float* W1 = (const float*)d_in[1];
    const float* b1 = (const float*)d_in[2];
    const float* W2 = (const float*)d_in[3];
    const float* b2 = (const float*)d_in[4];
    const int*  src = (const int*)d_in[5];
    const int*  dst = (const int*)d_in[6];

    const int N = in_sizes[0] / 256;
    const int E = in_sizes[5];

    float* out = (float*)d_out;

    // One-time stream/event creation (host-side only; no device memory).
    // Work launched is identical on every call — determinism preserved.
    static cudaStream_t s2 = nullptr;
    static cudaEvent_t ev_fork = nullptr, ev_join = nullptr;
    if (s2 == nullptr) {
        cudaStreamCreateWithFlags(&s2, cudaStreamNonBlocking);
        cudaEventCreateWithFlags(&ev_fork, cudaEventDisableTiming);
        cudaEventCreateWithFlags(&ev_join, cudaEventDisableTiming);
    }

    // --- fork: gemm1 (x,W1 only) on s2, concurrent with CSR build on default stream ---
    cudaEventRecord(ev_fork, 0);
    cudaStreamWaitEvent(s2, ev_fork, 0);
    gemm1_kernel<<<(N + 127) / 128, 256, 0, s2>>>(x, W1, N);
    cudaEventRecord(ev_join, s2);

    // --- CSR build chain on default stream ---
    zero_counts_kernel<<<(N + 255) / 256, 256>>>(N);
    degree_kernel<<<(E + 255) / 256, 256>>>(src, dst, E);
    rsqrt_kernel<<<(N + 255) / 256, 256>>>(N);
    {
        int nb = (N + SCAN_BLK - 1) / SCAN_BLK;
        scan_phase1_kernel<<<nb, SCAN_BLK>>>(N);
        scan_phase2_kernel<<<1, 128>>>(nb);
        scan_phase3_kernel<<<(N + 255) / 256, 256>>>(N);
    }
    bin_kernel<<<(E + 255) / 256, 256>>>(src, dst, E);

    // --- join: gather1 needs h1 + CSR + normalizers ---
    cudaStreamWaitEvent(0, ev_join, 0);
    gather1_kernel<<<(N + 7) / 8, 256>>>(b1, N);
    gemm2_kernel<<<(N + 31) / 32, 256>>>(W2, N);
    {
        long long tasks = (long long)N * 10;
        gather2_kernel<<<(int)((tasks + 255) / 256), 256>>>(b2, out, N);
    }
}

// round 7
// speedup vs baseline: 1.8898x; 1.0746x over previous
#include <cuda_runtime.h>
#include <cuda_fp16.h>
#include <cstdint>

#define N_MAX 100000
#define E_MAX 3200000
#define SCAN_BLK 1024
#define SCAN_NBLK ((N_MAX + SCAN_BLK - 1) / SCAN_BLK)   // 98

// ---------------- scratch (device globals; no allocation allowed) ----------------
__device__ __align__(128) __half g_h1[(size_t)N_MAX * 128];   // layer-1 messages, fp16
__device__ __align__(128) float  g_agg1[(size_t)N_MAX * 128]; // layer-1 result (activated+prenormed)
__device__ __align__(128) __half g_h2[(size_t)N_MAX * 40];    // layer-2 messages, fp16
__device__ int   g_din[N_MAX];           // raw in-degree (dst counts)
__device__ int   g_dout[N_MAX];          // raw out-degree (src counts)
__device__ float g_rso[N_MAX];           // rsqrt(max(deg_out,1))
__device__ float g_rsi[N_MAX];           // rsqrt(max(deg_in,1))
__device__ int   g_off[N_MAX + 1024];    // CSR row offsets (exclusive scan of g_din)
__device__ int   g_cursor[N_MAX];        // binning cursors
__device__ int   g_bsum[SCAN_NBLK + 32]; // scan block sums
__device__ int   g_csr_src[E_MAX];       // src node ids grouped by dst

// ---------------- zero degree counters ----------------
__global__ void zero_counts_kernel(int N) {
    int i = blockIdx.x * blockDim.x + threadIdx.x;
    if (i < N) { g_din[i] = 0; g_dout[i] = 0; }
}

// ---------------- degrees / histogram ----------------
__global__ void degree_kernel(const int* __restrict__ src, const int* __restrict__ dst, int E) {
    int e = blockIdx.x * blockDim.x + threadIdx.x;
    if (e < E) {
        atomicAdd(&g_dout[src[e]], 1);
        atomicAdd(&g_din[dst[e]], 1);
    }
}

__global__ void rsqrt_kernel(int N) {
    int i = blockIdx.x * blockDim.x + threadIdx.x;
    if (i < N) {
        g_rso[i] = rsqrtf((float)max(g_dout[i], 1));
        g_rsi[i] = rsqrtf((float)max(g_din[i], 1));
    }
}

// ---------------- scan (exclusive) of g_din into g_off, 3 phases ----------------
__global__ __launch_bounds__(SCAN_BLK) void scan_phase1_kernel(int N) {
    __shared__ int sh[SCAN_BLK];
    int i = blockIdx.x * SCAN_BLK + threadIdx.x;
    int v = (i < N) ? g_din[i] : 0;
    sh[threadIdx.x] = v;
    __syncthreads();
#pragma unroll
    for (int d = 1; d < SCAN_BLK; d <<= 1) {
        int t = (threadIdx.x >= d) ? sh[threadIdx.x - d] : 0;
        __syncthreads();
        sh[threadIdx.x] += t;
        __syncthreads();
    }
    if (i < N) g_off[i] = sh[threadIdx.x] - v;           // exclusive within block
    if (threadIdx.x == SCAN_BLK - 1) g_bsum[blockIdx.x] = sh[SCAN_BLK - 1];
}

__global__ __launch_bounds__(128) void scan_phase2_kernel(int nb) {
    __shared__ int sh[128];
    int t = threadIdx.x;
    int v = (t < nb) ? g_bsum[t] : 0;
    sh[t] = v;
    __syncthreads();
#pragma unroll
    for (int d = 1; d < 128; d <<= 1) {
        int x = (t >= d) ? sh[t - d] : 0;
        __syncthreads();
        sh[t] += x;
        __syncthreads();
    }
    if (t < nb) g_bsum[t] = sh[t] - v;                   // exclusive
}

__global__ void scan_phase3_kernel(int N) {
    int i = blockIdx.x * blockDim.x + threadIdx.x;
    if (i < N) {
        int o = g_off[i] + g_bsum[i >> 10];
        g_off[i] = o;
        g_cursor[i] = o;
    }
}

// ---------------- bin: group edge srcs by dst ----------------
__global__ void bin_kernel(const int* __restrict__ src, const int* __restrict__ dst, int E) {
    int e = blockIdx.x * blockDim.x + threadIdx.x;
    if (e < E) {
        int d = dst[e];
        int pos = atomicAdd(&g_cursor[d], 1);
        g_csr_src[pos] = src[e];
    }
}

// ---------------- GEMM1: h1 = x @ W1 (fp32 compute, fp16 store; no rso here) ----------------
// 128x128 block tile, BK=8, 256 threads, 8x8 micro-tile, 2-stage register prefetch.
__global__ __launch_bounds__(256, 2) void gemm1_kernel(const float* __restrict__ x,
                                                       const float* __restrict__ W1, int N) {
    __shared__ float As[8][128];   // k-major (transposed A tile)
    __shared__ float Bs[8][128];

    const int tid = threadIdx.x;
    const int block_row = blockIdx.x * 128;
    const int tr = tid >> 4;
    const int tc = tid & 15;

    const int a_row = tid >> 1;
    const int a_k4  = (tid & 1) * 4;
    const int g_row = block_row + a_row;
    const bool row_ok = (g_row < N);
    const float* a_base = x + (size_t)g_row * 256;

    const int b_k = tid >> 5;
    const int b_n = (tid & 31) * 4;

    float acc[8][8];
#pragma unroll
    for (int i = 0; i < 8; i++)
#pragma unroll
        for (int j = 0; j < 8; j++) acc[i][j] = 0.f;

    float4 av = make_float4(0.f, 0.f, 0.f, 0.f);
    if (row_ok) av = *reinterpret_cast<const float4*>(a_base + a_k4);
    float4 bv = *reinterpret_cast<const float4*>(W1 + (size_t)b_k * 128 + b_n);

    for (int k0 = 0; k0 < 256; k0 += 8) {
        As[a_k4 + 0][a_row] = av.x;
        As[a_k4 + 1][a_row] = av.y;
        As[a_k4 + 2][a_row] = av.z;
        As[a_k4 + 3][a_row] = av.w;
        *reinterpret_cast<float4*>(&Bs[b_k][b_n]) = bv;
        __syncthreads();

        if (k0 + 8 < 256) {
            if (row_ok) av = *reinterpret_cast<const float4*>(a_base + k0 + 8 + a_k4);
            bv = *reinterpret_cast<const float4*>(W1 + (size_t)(k0 + 8 + b_k) * 128 + b_n);
        }

#pragma unroll
        for (int k = 0; k < 8; k++) {
            float ar[8], br[8];
#pragma unroll
            for (int i = 0; i < 8; i++) ar[i] = As[k][tr * 8 + i];
#pragma unroll
            for (int j = 0; j < 8; j++) br[j] = Bs[k][tc * 8 + j];
#pragma unroll
            for (int i = 0; i < 8; i++)
#pragma unroll
                for (int j = 0; j < 8; j++) acc[i][j] = fmaf(ar[i], br[j], acc[i][j]);
        }
        __syncthreads();
    }

    // epilogue: convert each row's 8 cols to 4 half2 and store as one uint4 (16B aligned)
#pragma unroll
    for (int i = 0; i < 8; i++) {
        int r = block_row + tr * 8 + i;
        if (r < N) {
            __half2 h0 = __floats2half2_rn(acc[i][0], acc[i][1]);
            __half2 h1 = __floats2half2_rn(acc[i][2], acc[i][3]);
            __half2 h2 = __floats2half2_rn(acc[i][4], acc[i][5]);
            __half2 h3 = __floats2half2_rn(acc[i][6], acc[i][7]);
            uint4 pk;
            pk.x = *reinterpret_cast<unsigned*>(&h0);
            pk.y = *reinterpret_cast<unsigned*>(&h1);
            pk.z = *reinterpret_cast<unsigned*>(&h2);
            pk.w = *reinterpret_cast<unsigned*>(&h3);
            *reinterpret_cast<uint4*>(g_h1 + (size_t)r * 128 + tc * 8) = pk;
        }
    }
}

// ---------------- gather1: one warp per dst node, fp16 messages, fp32 accumulate --------------
// agg1[node] = relu( (sum_e rso[src_e] * h1[src_e]) * rsi + b1 ) * rso[node]
__global__ __launch_bounds__(256) void gather1_kernel(const float* __restrict__ b1, int N) {
    const int wid = threadIdx.x >> 5;
    const int lane = threadIdx.x & 31;
    const int node = blockIdx.x * 8 + wid;
    if (node >= N) return;

    const int start = g_off[node];
    const int cnt = g_din[node];
    const int* __restrict__ idx = g_csr_src + start;
    const size_t lo = (size_t)lane * 4;   // 4 halfs per lane = 8 bytes

    float4 acc = make_float4(0.f, 0.f, 0.f, 0.f);
    int i = 0;
    for (; i + 4 <= cnt; i += 4) {
        int s0 = idx[i], s1 = idx[i + 1], s2 = idx[i + 2], s3 = idx[i + 3];
        float w0 = g_rso[s0], w1 = g_rso[s1], w2 = g_rso[s2], w3 = g_rso[s3];
        uint2 p0 = *reinterpret_cast<const uint2*>(g_h1 + (size_t)s0 * 128 + lo);
        uint2 p1 = *reinterpret_cast<const uint2*>(g_h1 + (size_t)s1 * 128 + lo);
        uint2 p2 = *reinterpret_cast<const uint2*>(g_h1 + (size_t)s2 * 128 + lo);
        uint2 p3 = *reinterpret_cast<const uint2*>(g_h1 + (size_t)s3 * 128 + lo);
        float2 a0 = __half22float2(*reinterpret_cast<__half2*>(&p0.x));
        float2 b0 = __half22float2(*reinterpret_cast<__half2*>(&p0.y));
        float2 a1 = __half22float2(*reinterpret_cast<__half2*>(&p1.x));
        float2 b1_ = __half22float2(*reinterpret_cast<__half2*>(&p1.y));
        float2 a2 = __half22float2(*reinterpret_cast<__half2*>(&p2.x));
        float2 b2_ = __half22float2(*reinterpret_cast<__half2*>(&p2.y));
        float2 a3 = __half22float2(*reinterpret_cast<__half2*>(&p3.x));
        float2 b3_ = __half22float2(*reinterpret_cast<__half2*>(&p3.y));
        acc.x = fmaf(a0.x, w0, fmaf(a1.x, w1, fmaf(a2.x, w2, fmaf(a3.x, w3, acc.x))));
        acc.y = fmaf(a0.y, w0, fmaf(a1.y, w1, fmaf(a2.y, w2, fmaf(a3.y, w3, acc.y))));
        acc.z = fmaf(b0.x, w0, fmaf(b1_.x, w1, fmaf(b2_.x, w2, fmaf(b3_.x, w3, acc.z))));
        acc.w = fmaf(b0.y, w0, fmaf(b1_.y, w1, fmaf(b2_.y, w2, fmaf(b3_.y, w3, acc.w))));
    }
    for (; i < cnt; i++) {
        int s = idx[i];
        float w = g_rso[s];
        uint2 p = *reinterpret_cast<const uint2*>(g_h1 + (size_t)s * 128 + lo);
        float2 a = __half22float2(*reinterpret_cast<__half2*>(&p.x));
        float2 b = __half22float2(*reinterpret_cast<__half2*>(&p.y));
        acc.x = fmaf(a.x, w, acc.x);
        acc.y = fmaf(a.y, w, acc.y);
        acc.z = fmaf(b.x, w, acc.z);
        acc.w = fmaf(b.y, w, acc.w);
    }

    const float rsi = g_rsi[node];
    const float rso = g_rso[node];
    float4 bb = *reinterpret_cast<const float4*>(b1 + lane * 4);
    float4 r;
    r.x = fmaxf(fmaf(acc.x, rsi, bb.x), 0.f) * rso;
    r.y = fmaxf(fmaf(acc.y, rsi, bb.y), 0.f) * rso;
    r.z = fmaxf(fmaf(acc.z, rsi, bb.z), 0.f) * rso;
    r.w = fmaxf(fmaf(acc.w, rsi, bb.w), 0.f) * rso;
    *reinterpret_cast<float4*>(g_agg1 + (size_t)node * 128 + lane * 4) = r;
}

// ---------------- GEMM2: h2 = agg1 @ W2   [N,128]x[128,40], fp16 store ----------------
__global__ __launch_bounds__(256) void gemm2_kernel(const float* __restrict__ W2, int N) {
    __shared__ float As[32][129];
    __shared__ float Ws[128][40];

    const int tid = threadIdx.x;
    const int row0 = blockIdx.x * 32;

    for (int i = tid; i < 128 * 40; i += 256) Ws[i / 40][i % 40] = W2[i];

    for (int l = tid * 4; l < 32 * 128; l += 256 * 4) {
        int r = l >> 7;
        int k = l & 127;
        int gr = row0 + r;
        float4 v = make_float4(0.f, 0.f, 0.f, 0.f);
        if (gr < N) v = *reinterpret_cast<const float4*>(g_agg1 + (size_t)gr * 128 + k);
        As[r][k + 0] = v.x; As[r][k + 1] = v.y; As[r][k + 2] = v.z; As[r][k + 3] = v.w;
    }
    __syncthreads();

    const int row = tid & 31;
    const int cg = tid >> 5;        // 0..7 -> 5 columns each
    float acc[5];
#pragma unroll
    for (int j = 0; j < 5; j++) acc[j] = 0.f;

#pragma unroll 8
    for (int k = 0; k < 128; k++) {
        float a = As[row][k];
#pragma unroll
        for (int j = 0; j < 5; j++) acc[j] = fmaf(a, Ws[k][cg * 5 + j], acc[j]);
    }

    int gr = row0 + row;
    if (gr < N) {
#pragma unroll
        for (int j = 0; j < 5; j++)
            g_h2[(size_t)gr * 40 + cg * 5 + j] = __float2half_rn(acc[j]);
    }
}

// ---------------- gather2: 10 threads per dst node (4 halfs each), finalize fused -----------
// out[node] = (sum_e h2[src_e]) * rsi + b2
__global__ __launch_bounds__(256) void gather2_kernel(const float* __restrict__ b2,
                                                      float* __restrict__ out, int N) {
    int t = blockIdx.x * blockDim.x + threadIdx.x;
    int node = t / 10;
    int c = t - node * 10;
    if (node >= N) return;

    const int start = g_off[node];
    const int cnt = g_din[node];
    const int* __restrict__ idx = g_csr_src + start;
    const size_t co = (size_t)c * 4;   // 4 halfs = 8 bytes

    float4 acc = make_float4(0.f, 0.f, 0.f, 0.f);
    int i = 0;
    for (; i + 4 <= cnt; i += 4) {
        int s0 = idx[i], s1 = idx[i + 1], s2 = idx[i + 2], s3 = idx[i + 3];
        uint2 p0 = *reinterpret_cast<const uint2*>(g_h2 + (size_t)s0 * 40 + co);
        uint2 p1 = *reinterpret_cast<const uint2*>(g_h2 + (size_t)s1 * 40 + co);
        uint2 p2 = *reinterpret_cast<const uint2*>(g_h2 + (size_t)s2 * 40 + co);
        uint2 p3 = *reinterpret_cast<const uint2*>(g_h2 + (size_t)s3 * 40 + co);
        float2 a0 = __half22float2(*reinterpret_cast<__half2*>(&p0.x));
        float2 b0 = __half22float2(*reinterpret_cast<__half2*>(&p0.y));
        float2 a1 = __half22float2(*reinterpret_cast<__half2*>(&p1.x));
        float2 b1_ = __half22float2(*reinterpret_cast<__half2*>(&p1.y));
        float2 a2 = __half22float2(*reinterpret_cast<__half2*>(&p2.x));
        float2 b2_ = __half22float2(*reinterpret_cast<__half2*>(&p2.y));
        float2 a3 = __half22float2(*reinterpret_cast<__half2*>(&p3.x));
        float2 b3_ = __half22float2(*reinterpret_cast<__half2*>(&p3.y));
        acc.x += (a0.x + a1.x) + (a2.x + a3.x);
        acc.y += (a0.y + a1.y) + (a2.y + a3.y);
        acc.z += (b0.x + b1_.x) + (b2_.x + b3_.x);
        acc.w += (b0.y + b1_.y) + (b2_.y + b3_.y);
    }
    for (; i < cnt; i++) {
        int s = idx[i];
        uint2 p = *reinterpret_cast<const uint2*>(g_h2 + (size_t)s * 40 + co);
        float2 a = __half22float2(*reinterpret_cast<__half2*>(&p.x));
        float2 b = __half22float2(*reinterpret_cast<__half2*>(&p.y));
        acc.x += a.x; acc.y += a.y; acc.z += b.x; acc.w += b.y;
    }

    const float rsi = g_rsi[node];
    float4 bb = *reinterpret_cast<const float4*>(b2 + c * 4);
    float4 r;
    r.x = fmaf(acc.x, rsi, bb.x);
    r.y = fmaf(acc.y, rsi, bb.y);
    r.z = fmaf(acc.z, rsi, bb.z);
    r.w = fmaf(acc.w, rsi, bb.w);
    *reinterpret_cast<float4*>(out + (size_t)node * 40 + c * 4) = r;
}

// ---------------- launch (stream fork: gemm1 || CSR build) ----------------
extern "C" void kernel_launch(void* const* d_in, const int* in_sizes, int n_in,
                              void* d_out, int out_size) {
    const float* x  = (const float*)d_in[0];
    const float* W1 = (const float*)d_in[1];
    const float* b1 = (const float*)d_in[2];
    const float* W2 = (const float*)d_in[3];
    const float* b2 = (const float*)d_in[4];
    const int*  src = (const int*)d_in[5];
    const int*  dst = (const int*)d_in[6];

    const int N = in_sizes[0] / 256;
    const int E = in_sizes[5];

    float* out = (float*)d_out;

    static cudaStream_t s2 = nullptr;
    static cudaEvent_t ev_fork = nullptr, ev_join = nullptr;
    if (s2 == nullptr) {
        cudaStreamCreateWithFlags(&s2, cudaStreamNonBlocking);
        cudaEventCreateWithFlags(&ev_fork, cudaEventDisableTiming);
        cudaEventCreateWithFlags(&ev_join, cudaEventDisableTiming);
    }

    // --- fork: gemm1 (x,W1 only) on s2, concurrent with CSR build on default stream ---
    cudaEventRecord(ev_fork, 0);
    cudaStreamWaitEvent(s2, ev_fork, 0);
    gemm1_kernel<<<(N + 127) / 128, 256, 0, s2>>>(x, W1, N);
    cudaEventRecord(ev_join, s2);

    // --- CSR build chain on default stream ---
    zero_counts_kernel<<<(N + 255) / 256, 256>>>(N);
    degree_kernel<<<(E + 255) / 256, 256>>>(src, dst, E);
    rsqrt_kernel<<<(N + 255) / 256, 256>>>(N);
    {
        int nb = (N + SCAN_BLK - 1) / SCAN_BLK;
        scan_phase1_kernel<<<nb, SCAN_BLK>>>(N);
        scan_phase2_kernel<<<1, 128>>>(nb);
        scan_phase3_kernel<<<(N + 255) / 256, 256>>>(N);
    }
    bin_kernel<<<(E + 255) / 256, 256>>>(src, dst, E);

    // --- join: gather1 needs h1 + CSR + normalizers ---
    cudaStreamWaitEvent(0, ev_join, 0);
    gather1_kernel<<<(N + 7) / 8, 256>>>(b1, N);
    gemm2_kernel<<<(N + 31) / 32, 256>>>(W2, N);
    {
        long long tasks = (long long)N * 10;
        gather2_kernel<<<(int)((tasks + 255) / 256), 256>>>(b2, out, N);
    }
}

// round 8
// speedup vs baseline: 2.3999x; 1.2699x over previous
#include <cuda_runtime.h>
#include <cuda_fp16.h>
#include <cstdint>

#define N_MAX 100000
#define E_MAX 3200000
#define SCAN_BLK 1024
#define SCAN_NBLK ((N_MAX + SCAN_BLK - 1) / SCAN_BLK)   // 98

// ---------------- scratch (device globals; no allocation allowed) ----------------
__device__ __align__(128) __half g_h1[(size_t)N_MAX * 128];   // layer-1 messages, fp16
__device__ __align__(128) float  g_agg1[(size_t)N_MAX * 128]; // layer-1 result (activated+prenormed)
__device__ __align__(128) __half g_h2[(size_t)N_MAX * 40];    // layer-2 messages, fp16
__device__ int   g_din[N_MAX];
__device__ int   g_dout[N_MAX];
__device__ float g_rso[N_MAX];
__device__ float g_rsi[N_MAX];
__device__ int   g_off[N_MAX + 1024];
__device__ int   g_cursor[N_MAX];
__device__ int   g_bsum[SCAN_NBLK + 32];
__device__ int   g_csr_src[E_MAX];

// ---------------- zero degree counters ----------------
__global__ void zero_counts_kernel(int N) {
    int i = blockIdx.x * blockDim.x + threadIdx.x;
    if (i < N) { g_din[i] = 0; g_dout[i] = 0; }
}

// ---------------- degrees / histogram ----------------
__global__ void degree_kernel(const int* __restrict__ src, const int* __restrict__ dst, int E) {
    int e = blockIdx.x * blockDim.x + threadIdx.x;
    if (e < E) {
        atomicAdd(&g_dout[src[e]], 1);
        atomicAdd(&g_din[dst[e]], 1);
    }
}

__global__ void rsqrt_kernel(int N) {
    int i = blockIdx.x * blockDim.x + threadIdx.x;
    if (i < N) {
        g_rso[i] = rsqrtf((float)max(g_dout[i], 1));
        g_rsi[i] = rsqrtf((float)max(g_din[i], 1));
    }
}

// ---------------- scan (exclusive) of g_din into g_off, 3 phases ----------------
__global__ __launch_bounds__(SCAN_BLK) void scan_phase1_kernel(int N) {
    __shared__ int sh[SCAN_BLK];
    int i = blockIdx.x * SCAN_BLK + threadIdx.x;
    int v = (i < N) ? g_din[i] : 0;
    sh[threadIdx.x] = v;
    __syncthreads();
#pragma unroll
    for (int d = 1; d < SCAN_BLK; d <<= 1) {
        int t = (threadIdx.x >= d) ? sh[threadIdx.x - d] : 0;
        __syncthreads();
        sh[threadIdx.x] += t;
        __syncthreads();
    }
    if (i < N) g_off[i] = sh[threadIdx.x] - v;
    if (threadIdx.x == SCAN_BLK - 1) g_bsum[blockIdx.x] = sh[SCAN_BLK - 1];
}

__global__ __launch_bounds__(128) void scan_phase2_kernel(int nb) {
    __shared__ int sh[128];
    int t = threadIdx.x;
    int v = (t < nb) ? g_bsum[t] : 0;
    sh[t] = v;
    __syncthreads();
#pragma unroll
    for (int d = 1; d < 128; d <<= 1) {
        int x = (t >= d) ? sh[t - d] : 0;
        __syncthreads();
        sh[t] += x;
        __syncthreads();
    }
    if (t < nb) g_bsum[t] = sh[t] - v;
}

__global__ void scan_phase3_kernel(int N) {
    int i = blockIdx.x * blockDim.x + threadIdx.x;
    if (i < N) {
        int o = g_off[i] + g_bsum[i >> 10];
        g_off[i] = o;
        g_cursor[i] = o;
    }
}

// ---------------- bin: group edge srcs by dst ----------------
__global__ void bin_kernel(const int* __restrict__ src, const int* __restrict__ dst, int E) {
    int e = blockIdx.x * blockDim.x + threadIdx.x;
    if (e < E) {
        int d = dst[e];
        int pos = atomicAdd(&g_cursor[d], 1);
        g_csr_src[pos] = src[e];
    }
}

// ---------------- mma.m16n8k16 fp16 -> fp32 ----------------
__device__ __forceinline__ void mma_m16n8k16(float* c, const uint32_t* a, uint32_t b0, uint32_t b1) {
    asm volatile(
        "mma.sync.aligned.m16n8k16.row.col.f32.f16.f16.f32 "
        "{%0,%1,%2,%3}, {%4,%5,%6,%7}, {%8,%9}, {%0,%1,%2,%3};"
        : "+f"(c[0]), "+f"(c[1]), "+f"(c[2]), "+f"(c[3])
        : "r"(a[0]), "r"(a[1]), "r"(a[2]), "r"(a[3]), "r"(b0), "r"(b1));
}

// ---------------- GEMM1 (tensor cores): h1[fp16] = x @ W1   [N,256]x[256,128] ----------------
// 128x128 block tile, BK=32, 8 warps (4x2), warp tile 32x64, double-buffered smem.
// A smem [m][k], B smem [n][k] (transposed at staging), rows padded to 34 halfs (68B).
__global__ __launch_bounds__(256, 2) void gemm1_mma_kernel(const float* __restrict__ x,
                                                           const float* __restrict__ W1, int N) {
    __shared__ __half Asm[2][128][34];
    __shared__ __half Bsm[2][128][34];

    const int tid = threadIdx.x;
    const int lane = tid & 31;
    const int warp = tid >> 5;
    const int wm = warp & 3;        // 0..3 -> 32 rows each
    const int wn = warp >> 2;       // 0..1 -> 64 cols each
    const int block_row = blockIdx.x * 128;

    float c[2][8][4];
#pragma unroll
    for (int mt = 0; mt < 2; mt++)
#pragma unroll
        for (int nt = 0; nt < 8; nt++)
#pragma unroll
            for (int q = 0; q < 4; q++) c[mt][nt][q] = 0.f;

    // --- staging: load 128x32 of A (x, fp32->fp16) and 32x128 of B (W1, transposed) ---
    auto load_stage = [&](int k0, int buf) {
#pragma unroll
        for (int i = 0; i < 4; i++) {
            int l = tid + i * 256;          // 0..1023
            int r = l >> 3;                 // 0..127
            int c4 = (l & 7) * 4;           // 0..28
            int gr = block_row + r;
            float4 v = make_float4(0.f, 0.f, 0.f, 0.f);
            if (gr < N) v = *reinterpret_cast<const float4*>(x + (size_t)gr * 256 + k0 + c4);
            *reinterpret_cast<__half2*>(&Asm[buf][r][c4])     = __floats2half2_rn(v.x, v.y);
            *reinterpret_cast<__half2*>(&Asm[buf][r][c4 + 2]) = __floats2half2_rn(v.z, v.w);
        }
#pragma unroll
        for (int i = 0; i < 4; i++) {
            int l = tid + i * 256;
            int k = l >> 5;                 // 0..31
            int n4 = (l & 31) * 4;          // 0..124
            float4 v = *reinterpret_cast<const float4*>(W1 + (size_t)(k0 + k) * 128 + n4);
            Bsm[buf][n4 + 0][k] = __float2half_rn(v.x);
            Bsm[buf][n4 + 1][k] = __float2half_rn(v.y);
            Bsm[buf][n4 + 2][k] = __float2half_rn(v.z);
            Bsm[buf][n4 + 3][k] = __float2half_rn(v.w);
        }
    };

    auto compute = [&](int buf) {
#pragma unroll
        for (int ks = 0; ks < 2; ks++) {
            const int kb = ks * 16;
            const int acol = kb + (lane & 3) * 2;
            uint32_t a[2][4];
#pragma unroll
            for (int mt = 0; mt < 2; mt++) {
                int r = wm * 32 + mt * 16 + (lane >> 2);
                a[mt][0] = *reinterpret_cast<const uint32_t*>(&Asm[buf][r][acol]);
                a[mt][1] = *reinterpret_cast<const uint32_t*>(&Asm[buf][r + 8][acol]);
                a[mt][2] = *reinterpret_cast<const uint32_t*>(&Asm[buf][r][acol + 8]);
                a[mt][3] = *reinterpret_cast<const uint32_t*>(&Asm[buf][r + 8][acol + 8]);
            }
#pragma unroll
            for (int nt = 0; nt < 8; nt++) {
                int n = wn * 64 + nt * 8 + (lane >> 2);
                uint32_t b0 = *reinterpret_cast<const uint32_t*>(&Bsm[buf][n][acol]);
                uint32_t b1 = *reinterpret_cast<const uint32_t*>(&Bsm[buf][n][acol + 8]);
#pragma unroll
                for (int mt = 0; mt < 2; mt++) mma_m16n8k16(c[mt][nt], a[mt], b0, b1);
            }
        }
    };

    load_stage(0, 0);
    __syncthreads();
    int p = 0;
#pragma unroll
    for (int s = 0; s < 8; s++) {
        if (s < 7) load_stage((s + 1) * 32, p ^ 1);
        compute(p);
        __syncthreads();
        p ^= 1;
    }

    // --- epilogue: fp32 accum -> fp16 stores ---
#pragma unroll
    for (int mt = 0; mt < 2; mt++) {
        int r0 = block_row + wm * 32 + mt * 16 + (lane >> 2);
#pragma unroll
        for (int nt = 0; nt < 8; nt++) {
            int cc = wn * 64 + nt * 8 + (lane & 3) * 2;
            __half2 lo = __floats2half2_rn(c[mt][nt][0], c[mt][nt][1]);
            __half2 hi = __floats2half2_rn(c[mt][nt][2], c[mt][nt][3]);
            if (r0 < N)     *reinterpret_cast<__half2*>(g_h1 + (size_t)r0 * 128 + cc) = lo;
            if (r0 + 8 < N) *reinterpret_cast<__half2*>(g_h1 + (size_t)(r0 + 8) * 128 + cc) = hi;
        }
    }
}

// ---------------- gather1: one warp per dst node, fp16 messages, fp32 accumulate --------------
__global__ __launch_bounds__(256) void gather1_kernel(const float* __restrict__ b1, int N) {
    const int wid = threadIdx.x >> 5;
    const int lane = threadIdx.x & 31;
    const int node = blockIdx.x * 8 + wid;
    if (node >= N) return;

    const int start = g_off[node];
    const int cnt = g_din[node];
    const int* __restrict__ idx = g_csr_src + start;
    const size_t lo = (size_t)lane * 4;

    float4 acc = make_float4(0.f, 0.f, 0.f, 0.f);
    int i = 0;
    for (; i + 4 <= cnt; i += 4) {
        int s0 = idx[i], s1 = idx[i + 1], s2 = idx[i + 2], s3 = idx[i + 3];
        float w0 = g_rso[s0], w1 = g_rso[s1], w2 = g_rso[s2], w3 = g_rso[s3];
        uint2 p0 = *reinterpret_cast<const uint2*>(g_h1 + (size_t)s0 * 128 + lo);
        uint2 p1 = *reinterpret_cast<const uint2*>(g_h1 + (size_t)s1 * 128 + lo);
        uint2 p2 = *reinterpret_cast<const uint2*>(g_h1 + (size_t)s2 * 128 + lo);
        uint2 p3 = *reinterpret_cast<const uint2*>(g_h1 + (size_t)s3 * 128 + lo);
        float2 a0 = __half22float2(*reinterpret_cast<__half2*>(&p0.x));
        float2 b0 = __half22float2(*reinterpret_cast<__half2*>(&p0.y));
        float2 a1 = __half22float2(*reinterpret_cast<__half2*>(&p1.x));
        float2 b1_ = __half22float2(*reinterpret_cast<__half2*>(&p1.y));
        float2 a2 = __half22float2(*reinterpret_cast<__half2*>(&p2.x));
        float2 b2_ = __half22float2(*reinterpret_cast<__half2*>(&p2.y));
        float2 a3 = __half22float2(*reinterpret_cast<__half2*>(&p3.x));
        float2 b3_ = __half22float2(*reinterpret_cast<__half2*>(&p3.y));
        acc.x = fmaf(a0.x, w0, fmaf(a1.x, w1, fmaf(a2.x, w2, fmaf(a3.x, w3, acc.x))));
        acc.y = fmaf(a0.y, w0, fmaf(a1.y, w1, fmaf(a2.y, w2, fmaf(a3.y, w3, acc.y))));
        acc.z = fmaf(b0.x, w0, fmaf(b1_.x, w1, fmaf(b2_.x, w2, fmaf(b3_.x, w3, acc.z))));
        acc.w = fmaf(b0.y, w0, fmaf(b1_.y, w1, fmaf(b2_.y, w2, fmaf(b3_.y, w3, acc.w))));
    }
    for (; i < cnt; i++) {
        int s = idx[i];
        float w = g_rso[s];
        uint2 p = *reinterpret_cast<const uint2*>(g_h1 + (size_t)s * 128 + lo);
        float2 a = __half22float2(*reinterpret_cast<__half2*>(&p.x));
        float2 b = __half22float2(*reinterpret_cast<__half2*>(&p.y));
        acc.x = fmaf(a.x, w, acc.x);
        acc.y = fmaf(a.y, w, acc.y);
        acc.z = fmaf(b.x, w, acc.z);
        acc.w = fmaf(b.y, w, acc.w);
    }

    const float rsi = g_rsi[node];
    const float rso = g_rso[node];
    float4 bb = *reinterpret_cast<const float4*>(b1 + lane * 4);
    float4 r;
    r.x = fmaxf(fmaf(acc.x, rsi, bb.x), 0.f) * rso;
    r.y = fmaxf(fmaf(acc.y, rsi, bb.y), 0.f) * rso;
    r.z = fmaxf(fmaf(acc.z, rsi, bb.z), 0.f) * rso;
    r.w = fmaxf(fmaf(acc.w, rsi, bb.w), 0.f) * rso;
    *reinterpret_cast<float4*>(g_agg1 + (size_t)node * 128 + lane * 4) = r;
}

// ---------------- GEMM2: h2 = agg1 @ W2   [N,128]x[128,40], fp16 store ----------------
__global__ __launch_bounds__(256) void gemm2_kernel(const float* __restrict__ W2, int N) {
    __shared__ float As[32][129];
    __shared__ float Ws[128][40];

    const int tid = threadIdx.x;
    const int row0 = blockIdx.x * 32;

    for (int i = tid; i < 128 * 40; i += 256) Ws[i / 40][i % 40] = W2[i];

    for (int l = tid * 4; l < 32 * 128; l += 256 * 4) {
        int r = l >> 7;
        int k = l & 127;
        int gr = row0 + r;
        float4 v = make_float4(0.f, 0.f, 0.f, 0.f);
        if (gr < N) v = *reinterpret_cast<const float4*>(g_agg1 + (size_t)gr * 128 + k);
        As[r][k + 0] = v.x; As[r][k + 1] = v.y; As[r][k + 2] = v.z; As[r][k + 3] = v.w;
    }
    __syncthreads();

    const int row = tid & 31;
    const int cg = tid >> 5;
    float acc[5];
#pragma unroll
    for (int j = 0; j < 5; j++) acc[j] = 0.f;

#pragma unroll 8
    for (int k = 0; k < 128; k++) {
        float a = As[row][k];
#pragma unroll
        for (int j = 0; j < 5; j++) acc[j] = fmaf(a, Ws[k][cg * 5 + j], acc[j]);
    }

    int gr = row0 + row;
    if (gr < N) {
#pragma unroll
        for (int j = 0; j < 5; j++)
            g_h2[(size_t)gr * 40 + cg * 5 + j] = __float2half_rn(acc[j]);
    }
}

// ---------------- gather2: 10 threads per dst node, finalize fused ----------------
__global__ __launch_bounds__(256) void gather2_kernel(const float* __restrict__ b2,
                                                      float* __restrict__ out, int N) {
    int t = blockIdx.x * blockDim.x + threadIdx.x;
    int node = t / 10;
    int c = t - node * 10;
    if (node >= N) return;

    const int start = g_off[node];
    const int cnt = g_din[node];
    const int* __restrict__ idx = g_csr_src + start;
    const size_t co = (size_t)c * 4;

    float4 acc = make_float4(0.f, 0.f, 0.f, 0.f);
    int i = 0;
    for (; i + 4 <= cnt; i += 4) {
        int s0 = idx[i], s1 = idx[i + 1], s2 = idx[i + 2], s3 = idx[i + 3];
        uint2 p0 = *reinterpret_cast<const uint2*>(g_h2 + (size_t)s0 * 40 + co);
        uint2 p1 = *reinterpret_cast<const uint2*>(g_h2 + (size_t)s1 * 40 + co);
        uint2 p2 = *reinterpret_cast<const uint2*>(g_h2 + (size_t)s2 * 40 + co);
        uint2 p3 = *reinterpret_cast<const uint2*>(g_h2 + (size_t)s3 * 40 + co);
        float2 a0 = __half22float2(*reinterpret_cast<__half2*>(&p0.x));
        float2 b0 = __half22float2(*reinterpret_cast<__half2*>(&p0.y));
        float2 a1 = __half22float2(*reinterpret_cast<__half2*>(&p1.x));
        float2 b1_ = __half22float2(*reinterpret_cast<__half2*>(&p1.y));
        float2 a2 = __half22float2(*reinterpret_cast<__half2*>(&p2.x));
        float2 b2_ = __half22float2(*reinterpret_cast<__half2*>(&p2.y));
        float2 a3 = __half22float2(*reinterpret_cast<__half2*>(&p3.x));
        float2 b3_ = __half22float2(*reinterpret_cast<__half2*>(&p3.y));
        acc.x += (a0.x + a1.x) + (a2.x + a3.x);
        acc.y += (a0.y + a1.y) + (a2.y + a3.y);
        acc.z += (b0.x + b1_.x) + (b2_.x + b3_.x);
        acc.w += (b0.y + b1_.y) + (b2_.y + b3_.y);
    }
    for (; i < cnt; i++) {
        int s = idx[i];
        uint2 p = *reinterpret_cast<const uint2*>(g_h2 + (size_t)s * 40 + co);
        float2 a = __half22float2(*reinterpret_cast<__half2*>(&p.x));
        float2 b = __half22float2(*reinterpret_cast<__half2*>(&p.y));
        acc.x += a.x; acc.y += a.y; acc.z += b.x; acc.w += b.y;
    }

    const float rsi = g_rsi[node];
    float4 bb = *reinterpret_cast<const float4*>(b2 + c * 4);
    float4 r;
    r.x = fmaf(acc.x, rsi, bb.x);
    r.y = fmaf(acc.y, rsi, bb.y);
    r.z = fmaf(acc.z, rsi, bb.z);
    r.w = fmaf(acc.w, rsi, bb.w);
    *reinterpret_cast<float4*>(out + (size_t)node * 40 + c * 4) = r;
}

// ---------------- launch (stream fork: gemm1 || CSR build) ----------------
extern "C" void kernel_launch(void* const* d_in, const int* in_sizes, int n_in,
                              void* d_out, int out_size) {
    const float* x  = (const float*)d_in[0];
    const float* W1 = (const float*)d_in[1];
    const float* b1 = (const float*)d_in[2];
    const float* W2 = (const float*)d_in[3];
    const float* b2 = (const float*)d_in[4];
    const int*  src = (const int*)d_in[5];
    const int*  dst = (const int*)d_in[6];

    const int N = in_sizes[0] / 256;
    const int E = in_sizes[5];

    float* out = (float*)d_out;

    static cudaStream_t s2 = nullptr;
    static cudaEvent_t ev_fork = nullptr, ev_join = nullptr;
    if (s2 == nullptr) {
        cudaStreamCreateWithFlags(&s2, cudaStreamNonBlocking);
        cudaEventCreateWithFlags(&ev_fork, cudaEventDisableTiming);
        cudaEventCreateWithFlags(&ev_join, cudaEventDisableTiming);
    }

    // --- fork: gemm1 (x,W1 only) on s2, concurrent with CSR build on default stream ---
    cudaEventRecord(ev_fork, 0);
    cudaStreamWaitEvent(s2, ev_fork, 0);
    gemm1_mma_kernel<<<(N + 127) / 128, 256, 0, s2>>>(x, W1, N);
    cudaEventRecord(ev_join, s2);

    // --- CSR build chain on default stream ---
    zero_counts_kernel<<<(N + 255) / 256, 256>>>(N);
    degree_kernel<<<(E + 255) / 256, 256>>>(src, dst, E);
    rsqrt_kernel<<<(N + 255) / 256, 256>>>(N);
    {
        int nb = (N + SCAN_BLK - 1) / SCAN_BLK;
        scan_phase1_kernel<<<nb, SCAN_BLK>>>(N);
        scan_phase2_kernel<<<1, 128>>>(nb);
        scan_phase3_kernel<<<(N + 255) / 256, 256>>>(N);
    }
    bin_kernel<<<(E + 255) / 256, 256>>>(src, dst, E);

    // --- join: gather1 needs h1 + CSR + normalizers ---
    cudaStreamWaitEvent(0, ev_join, 0);
    gather1_kernel<<<(N + 7) / 8, 256>>>(b1, N);
    gemm2_kernel<<<(N + 31) / 32, 256>>>(W2, N);
    {
        long long tasks = (long long)N * 10;
        gather2_kernel<<<(int)((tasks + 255) / 256), 256>>>(b2, out, N);
    }
}

// round 9
// speedup vs baseline: 3.1543x; 1.3143x over previous
#include <cuda_runtime.h>
#include <cuda_fp16.h>
#include <cstdint>

#define N_MAX 100000
#define E_MAX 3200000
#define SCAN_BLK 1024
#define SCAN_NBLK ((N_MAX + SCAN_BLK - 1) / SCAN_BLK)   // 98

// ---------------- scratch (device globals; no allocation allowed) ----------------
__device__ __align__(128) __half g_h1[(size_t)N_MAX * 128];   // layer-1 messages, fp16
__device__ __align__(128) float  g_agg1[(size_t)N_MAX * 128]; // layer-1 result (activated+prenormed)
__device__ __align__(128) __half g_h2[(size_t)N_MAX * 40];    // layer-2 messages, fp16
__device__ int   g_din[N_MAX];
__device__ int   g_dout[N_MAX];
__device__ float g_rso[N_MAX];
__device__ float g_rsi[N_MAX];
__device__ int   g_off[N_MAX + 1024];
__device__ int   g_cursor[N_MAX];
__device__ int   g_bsum[SCAN_NBLK + 32];
__device__ int   g_csr_src[E_MAX];

// ---------------- zero degree counters ----------------
__global__ void zero_counts_kernel(int N) {
    int i = blockIdx.x * blockDim.x + threadIdx.x;
    if (i < N) { g_din[i] = 0; g_dout[i] = 0; }
}

// ---------------- degrees / histogram ----------------
__global__ void degree_kernel(const int* __restrict__ src, const int* __restrict__ dst, int E) {
    int e = blockIdx.x * blockDim.x + threadIdx.x;
    if (e < E) {
        atomicAdd(&g_dout[src[e]], 1);
        atomicAdd(&g_din[dst[e]], 1);
    }
}

// ---------------- scan (exclusive) of g_din into g_off, 3 phases ----------------
__global__ __launch_bounds__(SCAN_BLK) void scan_phase1_kernel(int N) {
    __shared__ int sh[SCAN_BLK];
    int i = blockIdx.x * SCAN_BLK + threadIdx.x;
    int v = (i < N) ? g_din[i] : 0;
    sh[threadIdx.x] = v;
    __syncthreads();
#pragma unroll
    for (int d = 1; d < SCAN_BLK; d <<= 1) {
        int t = (threadIdx.x >= d) ? sh[threadIdx.x - d] : 0;
        __syncthreads();
        sh[threadIdx.x] += t;
        __syncthreads();
    }
    if (i < N) g_off[i] = sh[threadIdx.x] - v;
    if (threadIdx.x == SCAN_BLK - 1) g_bsum[blockIdx.x] = sh[SCAN_BLK - 1];
}

__global__ __launch_bounds__(128) void scan_phase2_kernel(int nb) {
    __shared__ int sh[128];
    int t = threadIdx.x;
    int v = (t < nb) ? g_bsum[t] : 0;
    sh[t] = v;
    __syncthreads();
#pragma unroll
    for (int d = 1; d < 128; d <<= 1) {
        int x = (t >= d) ? sh[t - d] : 0;
        __syncthreads();
        sh[t] += x;
        __syncthreads();
    }
    if (t < nb) g_bsum[t] = sh[t] - v;
}

// phase3 also computes the rsqrt normalizers (folds old rsqrt_kernel)
__global__ void scan_phase3_kernel(int N) {
    int i = blockIdx.x * blockDim.x + threadIdx.x;
    if (i < N) {
        int o = g_off[i] + g_bsum[i >> 10];
        g_off[i] = o;
        g_cursor[i] = o;
        g_rso[i] = rsqrtf((float)max(g_dout[i], 1));
        g_rsi[i] = rsqrtf((float)max(g_din[i], 1));
    }
}

// ---------------- bin: group edge srcs by dst ----------------
__global__ void bin_kernel(const int* __restrict__ src, const int* __restrict__ dst, int E) {
    int e = blockIdx.x * blockDim.x + threadIdx.x;
    if (e < E) {
        int d = dst[e];
        int pos = atomicAdd(&g_cursor[d], 1);
        g_csr_src[pos] = src[e];
    }
}

// ---------------- mma.m16n8k16 fp16 -> fp32 ----------------
__device__ __forceinline__ void mma_m16n8k16(float* c, const uint32_t* a, uint32_t b0, uint32_t b1) {
    asm volatile(
        "mma.sync.aligned.m16n8k16.row.col.f32.f16.f16.f32 "
        "{%0,%1,%2,%3}, {%4,%5,%6,%7}, {%8,%9}, {%0,%1,%2,%3};"
        : "+f"(c[0]), "+f"(c[1]), "+f"(c[2]), "+f"(c[3])
        : "r"(a[0]), "r"(a[1]), "r"(a[2]), "r"(a[3]), "r"(b0), "r"(b1));
}

// ---------------- GEMM1 (tensor cores): h1[fp16] = x @ W1   [N,256]x[256,128] ----------------
__global__ __launch_bounds__(256, 2) void gemm1_mma_kernel(const float* __restrict__ x,
                                                           const float* __restrict__ W1, int N) {
    __shared__ __half Asm[2][128][34];
    __shared__ __half Bsm[2][128][34];

    const int tid = threadIdx.x;
    const int lane = tid & 31;
    const int warp = tid >> 5;
    const int wm = warp & 3;
    const int wn = warp >> 2;
    const int block_row = blockIdx.x * 128;

    float c[2][8][4];
#pragma unroll
    for (int mt = 0; mt < 2; mt++)
#pragma unroll
        for (int nt = 0; nt < 8; nt++)
#pragma unroll
            for (int q = 0; q < 4; q++) c[mt][nt][q] = 0.f;

    auto load_stage = [&](int k0, int buf) {
#pragma unroll
        for (int i = 0; i < 4; i++) {
            int l = tid + i * 256;
            int r = l >> 3;
            int c4 = (l & 7) * 4;
            int gr = block_row + r;
            float4 v = make_float4(0.f, 0.f, 0.f, 0.f);
            if (gr < N) v = *reinterpret_cast<const float4*>(x + (size_t)gr * 256 + k0 + c4);
            *reinterpret_cast<__half2*>(&Asm[buf][r][c4])     = __floats2half2_rn(v.x, v.y);
            *reinterpret_cast<__half2*>(&Asm[buf][r][c4 + 2]) = __floats2half2_rn(v.z, v.w);
        }
#pragma unroll
        for (int i = 0; i < 4; i++) {
            int l = tid + i * 256;
            int k = l >> 5;
            int n4 = (l & 31) * 4;
            float4 v = *reinterpret_cast<const float4*>(W1 + (size_t)(k0 + k) * 128 + n4);
            Bsm[buf][n4 + 0][k] = __float2half_rn(v.x);
            Bsm[buf][n4 + 1][k] = __float2half_rn(v.y);
            Bsm[buf][n4 + 2][k] = __float2half_rn(v.z);
            Bsm[buf][n4 + 3][k] = __float2half_rn(v.w);
        }
    };

    auto compute = [&](int buf) {
#pragma unroll
        for (int ks = 0; ks < 2; ks++) {
            const int acol = ks * 16 + (lane & 3) * 2;
            uint32_t a[2][4];
#pragma unroll
            for (int mt = 0; mt < 2; mt++) {
                int r = wm * 32 + mt * 16 + (lane >> 2);
                a[mt][0] = *reinterpret_cast<const uint32_t*>(&Asm[buf][r][acol]);
                a[mt][1] = *reinterpret_cast<const uint32_t*>(&Asm[buf][r + 8][acol]);
                a[mt][2] = *reinterpret_cast<const uint32_t*>(&Asm[buf][r][acol + 8]);
                a[mt][3] = *reinterpret_cast<const uint32_t*>(&Asm[buf][r + 8][acol + 8]);
            }
#pragma unroll
            for (int nt = 0; nt < 8; nt++) {
                int n = wn * 64 + nt * 8 + (lane >> 2);
                uint32_t b0 = *reinterpret_cast<const uint32_t*>(&Bsm[buf][n][acol]);
                uint32_t b1 = *reinterpret_cast<const uint32_t*>(&Bsm[buf][n][acol + 8]);
#pragma unroll
                for (int mt = 0; mt < 2; mt++) mma_m16n8k16(c[mt][nt], a[mt], b0, b1);
            }
        }
    };

    load_stage(0, 0);
    __syncthreads();
    int p = 0;
#pragma unroll
    for (int s = 0; s < 8; s++) {
        if (s < 7) load_stage((s + 1) * 32, p ^ 1);
        compute(p);
        __syncthreads();
        p ^= 1;
    }

#pragma unroll
    for (int mt = 0; mt < 2; mt++) {
        int r0 = block_row + wm * 32 + mt * 16 + (lane >> 2);
#pragma unroll
        for (int nt = 0; nt < 8; nt++) {
            int cc = wn * 64 + nt * 8 + (lane & 3) * 2;
            __half2 lo = __floats2half2_rn(c[mt][nt][0], c[mt][nt][1]);
            __half2 hi = __floats2half2_rn(c[mt][nt][2], c[mt][nt][3]);
            if (r0 < N)     *reinterpret_cast<__half2*>(g_h1 + (size_t)r0 * 128 + cc) = lo;
            if (r0 + 8 < N) *reinterpret_cast<__half2*>(g_h1 + (size_t)(r0 + 8) * 128 + cc) = hi;
        }
    }
}

// ---------------- gather1: one warp per dst node, fp16 messages, fp32 accumulate --------------
__global__ __launch_bounds__(256) void gather1_kernel(const float* __restrict__ b1, int N) {
    const int wid = threadIdx.x >> 5;
    const int lane = threadIdx.x & 31;
    const int node = blockIdx.x * 8 + wid;
    if (node >= N) return;

    const int start = g_off[node];
    const int cnt = g_din[node];
    const int* __restrict__ idx = g_csr_src + start;
    const size_t lo = (size_t)lane * 4;

    float4 acc = make_float4(0.f, 0.f, 0.f, 0.f);
    int i = 0;
    for (; i + 4 <= cnt; i += 4) {
        int s0 = idx[i], s1 = idx[i + 1], s2 = idx[i + 2], s3 = idx[i + 3];
        float w0 = g_rso[s0], w1 = g_rso[s1], w2 = g_rso[s2], w3 = g_rso[s3];
        uint2 p0 = *reinterpret_cast<const uint2*>(g_h1 + (size_t)s0 * 128 + lo);
        uint2 p1 = *reinterpret_cast<const uint2*>(g_h1 + (size_t)s1 * 128 + lo);
        uint2 p2 = *reinterpret_cast<const uint2*>(g_h1 + (size_t)s2 * 128 + lo);
        uint2 p3 = *reinterpret_cast<const uint2*>(g_h1 + (size_t)s3 * 128 + lo);
        float2 a0 = __half22float2(*reinterpret_cast<__half2*>(&p0.x));
        float2 b0 = __half22float2(*reinterpret_cast<__half2*>(&p0.y));
        float2 a1 = __half22float2(*reinterpret_cast<__half2*>(&p1.x));
        float2 b1_ = __half22float2(*reinterpret_cast<__half2*>(&p1.y));
        float2 a2 = __half22float2(*reinterpret_cast<__half2*>(&p2.x));
        float2 b2_ = __half22float2(*reinterpret_cast<__half2*>(&p2.y));
        float2 a3 = __half22float2(*reinterpret_cast<__half2*>(&p3.x));
        float2 b3_ = __half22float2(*reinterpret_cast<__half2*>(&p3.y));
        acc.x = fmaf(a0.x, w0, fmaf(a1.x, w1, fmaf(a2.x, w2, fmaf(a3.x, w3, acc.x))));
        acc.y = fmaf(a0.y, w0, fmaf(a1.y, w1, fmaf(a2.y, w2, fmaf(a3.y, w3, acc.y))));
        acc.z = fmaf(b0.x, w0, fmaf(b1_.x, w1, fmaf(b2_.x, w2, fmaf(b3_.x, w3, acc.z))));
        acc.w = fmaf(b0.y, w0, fmaf(b1_.y, w1, fmaf(b2_.y, w2, fmaf(b3_.y, w3, acc.w))));
    }
    for (; i < cnt; i++) {
        int s = idx[i];
        float w = g_rso[s];
        uint2 p = *reinterpret_cast<const uint2*>(g_h1 + (size_t)s * 128 + lo);
        float2 a = __half22float2(*reinterpret_cast<__half2*>(&p.x));
        float2 b = __half22float2(*reinterpret_cast<__half2*>(&p.y));
        acc.x = fmaf(a.x, w, acc.x);
        acc.y = fmaf(a.y, w, acc.y);
        acc.z = fmaf(b.x, w, acc.z);
        acc.w = fmaf(b.y, w, acc.w);
    }

    const float rsi = g_rsi[node];
    const float rso = g_rso[node];
    float4 bb = *reinterpret_cast<const float4*>(b1 + lane * 4);
    float4 r;
    r.x = fmaxf(fmaf(acc.x, rsi, bb.x), 0.f) * rso;
    r.y = fmaxf(fmaf(acc.y, rsi, bb.y), 0.f) * rso;
    r.z = fmaxf(fmaf(acc.z, rsi, bb.z), 0.f) * rso;
    r.w = fmaxf(fmaf(acc.w, rsi, bb.w), 0.f) * rso;
    *reinterpret_cast<float4*>(g_agg1 + (size_t)node * 128 + lane * 4) = r;
}

// ---------------- GEMM2 (tensor cores): h2[fp16] = agg1 @ W2   [N,128]x[128,40] ----------------
// 128x64 block tile (N padded 40->64 with zeros), K=128 in two BK=64 chunks.
// 8 warps: wm=warp&3 (32 rows), wn=warp>>2 (32 cols); warp tile 32x32 (mt 2 x nt 4).
__global__ __launch_bounds__(256) void gemm2_mma_kernel(const float* __restrict__ W2, int N) {
    __shared__ __half Ah[128][72];   // 128 rows x BK=64 (+8 pad)
    __shared__ __half Wh[64][72];    // 64 padded n-cols x BK=64 (+8 pad)

    const int tid = threadIdx.x;
    const int lane = tid & 31;
    const int warp = tid >> 5;
    const int wm = warp & 3;
    const int wn = warp >> 2;
    const int block_row = blockIdx.x * 128;

    float c[2][4][4];
#pragma unroll
    for (int mt = 0; mt < 2; mt++)
#pragma unroll
        for (int nt = 0; nt < 4; nt++)
#pragma unroll
            for (int q = 0; q < 4; q++) c[mt][nt][q] = 0.f;

#pragma unroll
    for (int kc = 0; kc < 2; kc++) {
        const int k0 = kc * 64;
        // stage A: 128x64 floats -> fp16 (2048 float4, 8 per thread)
#pragma unroll
        for (int i = 0; i < 8; i++) {
            int l = i * 256 + tid;
            int r = l >> 4;              // 16 float4 per 64-float row
            int c4 = (l & 15) * 4;
            int gr = block_row + r;
            float4 v = make_float4(0.f, 0.f, 0.f, 0.f);
            if (gr < N) v = *reinterpret_cast<const float4*>(g_agg1 + (size_t)gr * 128 + k0 + c4);
            *reinterpret_cast<__half2*>(&Ah[r][c4])     = __floats2half2_rn(v.x, v.y);
            *reinterpret_cast<__half2*>(&Ah[r][c4 + 2]) = __floats2half2_rn(v.z, v.w);
        }
        // stage W2 transposed + zero-padded: Wh[n][k] = W2[(k0+k)*40+n] (n<40)
#pragma unroll
        for (int i = 0; i < 16; i++) {
            int l = i * 256 + tid;       // 0..4095
            int n = l >> 6;
            int k = l & 63;
            Wh[n][k] = (n < 40) ? __float2half_rn(W2[(size_t)(k0 + k) * 40 + n]) : __half(0);
        }
        __syncthreads();

#pragma unroll
        for (int ks = 0; ks < 4; ks++) {
            const int acol = ks * 16 + (lane & 3) * 2;
            uint32_t a[2][4];
#pragma unroll
            for (int mt = 0; mt < 2; mt++) {
                int r = wm * 32 + mt * 16 + (lane >> 2);
                a[mt][0] = *reinterpret_cast<const uint32_t*>(&Ah[r][acol]);
                a[mt][1] = *reinterpret_cast<const uint32_t*>(&Ah[r + 8][acol]);
                a[mt][2] = *reinterpret_cast<const uint32_t*>(&Ah[r][acol + 8]);
                a[mt][3] = *reinterpret_cast<const uint32_t*>(&Ah[r + 8][acol + 8]);
            }
#pragma unroll
            for (int nt = 0; nt < 4; nt++) {
                int n = wn * 32 + nt * 8 + (lane >> 2);
                uint32_t b0 = *reinterpret_cast<const uint32_t*>(&Wh[n][acol]);
                uint32_t b1 = *reinterpret_cast<const uint32_t*>(&Wh[n][acol + 8]);
#pragma unroll
                for (int mt = 0; mt < 2; mt++) mma_m16n8k16(c[mt][nt], a[mt], b0, b1);
            }
        }
        __syncthreads();
    }

    // epilogue: only columns < 40 exist in g_h2
#pragma unroll
    for (int mt = 0; mt < 2; mt++) {
        int r0 = block_row + wm * 32 + mt * 16 + (lane >> 2);
#pragma unroll
        for (int nt = 0; nt < 4; nt++) {
            int cc = wn * 32 + nt * 8 + (lane & 3) * 2;
            if (cc < 40) {
                __half2 lo = __floats2half2_rn(c[mt][nt][0], c[mt][nt][1]);
                __half2 hi = __floats2half2_rn(c[mt][nt][2], c[mt][nt][3]);
                if (r0 < N)     *reinterpret_cast<__half2*>(g_h2 + (size_t)r0 * 40 + cc) = lo;
                if (r0 + 8 < N) *reinterpret_cast<__half2*>(g_h2 + (size_t)(r0 + 8) * 40 + cc) = hi;
            }
        }
    }
}

// ---------------- gather2: 10 threads per dst node, finalize fused ----------------
__global__ __launch_bounds__(256) void gather2_kernel(const float* __restrict__ b2,
                                                      float* __restrict__ out, int N) {
    int t = blockIdx.x * blockDim.x + threadIdx.x;
    int node = t / 10;
    int c = t - node * 10;
    if (node >= N) return;

    const int start = g_off[node];
    const int cnt = g_din[node];
    const int* __restrict__ idx = g_csr_src + start;
    const size_t co = (size_t)c * 4;

    float4 acc = make_float4(0.f, 0.f, 0.f, 0.f);
    int i = 0;
    for (; i + 4 <= cnt; i += 4) {
        int s0 = idx[i], s1 = idx[i + 1], s2 = idx[i + 2], s3 = idx[i + 3];
        uint2 p0 = *reinterpret_cast<const uint2*>(g_h2 + (size_t)s0 * 40 + co);
        uint2 p1 = *reinterpret_cast<const uint2*>(g_h2 + (size_t)s1 * 40 + co);
        uint2 p2 = *reinterpret_cast<const uint2*>(g_h2 + (size_t)s2 * 40 + co);
        uint2 p3 = *reinterpret_cast<const uint2*>(g_h2 + (size_t)s3 * 40 + co);
        float2 a0 = __half22float2(*reinterpret_cast<__half2*>(&p0.x));
        float2 b0 = __half22float2(*reinterpret_cast<__half2*>(&p0.y));
        float2 a1 = __half22float2(*reinterpret_cast<__half2*>(&p1.x));
        float2 b1_ = __half22float2(*reinterpret_cast<__half2*>(&p1.y));
        float2 a2 = __half22float2(*reinterpret_cast<__half2*>(&p2.x));
        float2 b2_ = __half22float2(*reinterpret_cast<__half2*>(&p2.y));
        float2 a3 = __half22float2(*reinterpret_cast<__half2*>(&p3.x));
        float2 b3_ = __half22float2(*reinterpret_cast<__half2*>(&p3.y));
        acc.x += (a0.x + a1.x) + (a2.x + a3.x);
        acc.y += (a0.y + a1.y) + (a2.y + a3.y);
        acc.z += (b0.x + b1_.x) + (b2_.x + b3_.x);
        acc.w += (b0.y + b1_.y) + (b2_.y + b3_.y);
    }
    for (; i < cnt; i++) {
        int s = idx[i];
        uint2 p = *reinterpret_cast<const uint2*>(g_h2 + (size_t)s * 40 + co);
        float2 a = __half22float2(*reinterpret_cast<__half2*>(&p.x));
        float2 b = __half22float2(*reinterpret_cast<__half2*>(&p.y));
        acc.x += a.x; acc.y += a.y; acc.z += b.x; acc.w += b.y;
    }

    const float rsi = g_rsi[node];
    float4 bb = *reinterpret_cast<const float4*>(b2 + c * 4);
    float4 r;
    r.x = fmaf(acc.x, rsi, bb.x);
    r.y = fmaf(acc.y, rsi, bb.y);
    r.z = fmaf(acc.z, rsi, bb.z);
    r.w = fmaf(acc.w, rsi, bb.w);
    *reinterpret_cast<float4*>(out + (size_t)node * 40 + c * 4) = r;
}

// ---------------- launch (stream fork: gemm1 || CSR build) ----------------
extern "C" void kernel_launch(void* const* d_in, const int* in_sizes, int n_in,
                              void* d_out, int out_size) {
    const float* x  = (const float*)d_in[0];
    const float* W1 = (const float*)d_in[1];
    const float* b1 = (const float*)d_in[2];
    const float* W2 = (const float*)d_in[3];
    const float* b2 = (const float*)d_in[4];
    const int*  src = (const int*)d_in[5];
    const int*  dst = (const int*)d_in[6];

    const int N = in_sizes[0] / 256;
    const int E = in_sizes[5];

    float* out = (float*)d_out;

    static cudaStream_t s2 = nullptr;
    static cudaEvent_t ev_fork = nullptr, ev_join = nullptr;
    if (s2 == nullptr) {
        cudaStreamCreateWithFlags(&s2, cudaStreamNonBlocking);
        cudaEventCreateWithFlags(&ev_fork, cudaEventDisableTiming);
        cudaEventCreateWithFlags(&ev_join, cudaEventDisableTiming);
    }

    // --- fork: gemm1 (x,W1 only) on s2, concurrent with CSR build on default stream ---
    cudaEventRecord(ev_fork, 0);
    cudaStreamWaitEvent(s2, ev_fork, 0);
    gemm1_mma_kernel<<<(N + 127) / 128, 256, 0, s2>>>(x, W1, N);
    cudaEventRecord(ev_join, s2);

    // --- CSR build chain on default stream ---
    zero_counts_kernel<<<(N + 255) / 256, 256>>>(N);
    degree_kernel<<<(E + 255) / 256, 256>>>(src, dst, E);
    {
        int nb = (N + SCAN_BLK - 1) / SCAN_BLK;
        scan_phase1_kernel<<<nb, SCAN_BLK>>>(N);
        scan_phase2_kernel<<<1, 128>>>(nb);
        scan_phase3_kernel<<<(N + 255) / 256, 256>>>(N);   // also rsqrt normalizers
    }
    bin_kernel<<<(E + 255) / 256, 256>>>(src, dst, E);

    // --- join: gather1 needs h1 + CSR + normalizers ---
    cudaStreamWaitEvent(0, ev_join, 0);
    gather1_kernel<<<(N + 7) / 8, 256>>>(b1, N);
    gemm2_mma_kernel<<<(N + 127) / 128, 256>>>(W2, N);
    {
        long long tasks = (long long)N * 10;
        gather2_kernel<<<(int)((tasks + 255) / 256), 256>>>(b2, out, N);
    }
}